// round 2
// baseline (speedup 1.0000x reference)
#include <cuda_runtime.h>
#include <cstdint>

// Problem dims (fixed by reference)
#define B_   2
#define S_   2048
#define D_   1024
#define H_   16
#define HD_  64
#define NTOK (B_ * S_)   // 4096

// ---------------- scratch (no cudaMalloc allowed) ----------------
__device__ float g_Qp[(size_t)NTOK * D_];
__device__ float g_Kp[(size_t)NTOK * D_];
__device__ float g_Vp[(size_t)NTOK * D_];
__device__ float g_X [(size_t)NTOK * D_];
__device__ float g_mbias[NTOK];

// =================================================================
// Mask build: combined additive bias over key axis.
// Auto-detects whether masks arrived as uint8 (1B) or int32 (4B):
// reinterpret first 4096 bytes as 1024 ints (safe either way). If
// any value > 1, the data must be packed uint8.
// One block, 1024 threads.
// =================================================================
__global__ void build_mask(const void* __restrict__ kpm_raw,
                           const void* __restrict__ am_raw,
                           float* __restrict__ mb) {
    __shared__ int s_u8;
    if (threadIdx.x == 0) s_u8 = 0;
    __syncthreads();

    const int* probe = (const int*)kpm_raw;
    for (int i = threadIdx.x; i < 1024; i += blockDim.x)
        if ((unsigned)probe[i] > 1u) s_u8 = 1;   // benign race: same value
    __syncthreads();
    const int is_u8 = s_u8;

    for (int i = threadIdx.x; i < NTOK; i += blockDim.x) {
        int k, a;
        if (is_u8) {
            k = ((const uint8_t*)kpm_raw)[i];
            a = ((const uint8_t*)am_raw)[i];
        } else {
            k = ((const int*)kpm_raw)[i];
            a = ((const int*)am_raw)[i];
        }
        mb[i] = (k | a) ? -1e30f : 0.0f;
    }
}

// =================================================================
// GEMM: C[m,n] = sum_k A[m,k] * W[n,k] + bias[n]
// A: M x K row-major, W: N x K row-major (torch Linear weight layout)
// 128x128 tile, BK=16, 256 threads, 8x8 per thread.
// =================================================================
#define GBM 128
#define GBN 128
#define GBK 16

__global__ __launch_bounds__(256, 2)
void gemm_abt_bias(const float* __restrict__ A, const float* __restrict__ W,
                   const float* __restrict__ bias, float* __restrict__ C,
                   int M, int N, int K) {
    __shared__ __align__(16) float As[GBK][GBM];
    __shared__ __align__(16) float Bs[GBK][GBN];

    const int tid = threadIdx.x;
    const int tx = tid & 15;        // 0..15  -> N micro
    const int ty = tid >> 4;        // 0..15  -> M micro

    const float* Ab = A + (size_t)blockIdx.y * GBM * K;
    const float* Wb = W + (size_t)blockIdx.x * GBN * K;

    float acc[8][8] = {};

    const int lr = tid >> 2;            // 0..63
    const int lc = (tid & 3) << 2;      // 0,4,8,12

    for (int k0 = 0; k0 < K; k0 += GBK) {
#pragma unroll
        for (int r = 0; r < 2; r++) {
            const int row = lr + r * 64;
            float4 va = *(const float4*)(Ab + (size_t)row * K + k0 + lc);
            As[lc + 0][row] = va.x;
            As[lc + 1][row] = va.y;
            As[lc + 2][row] = va.z;
            As[lc + 3][row] = va.w;
            float4 vb = *(const float4*)(Wb + (size_t)row * K + k0 + lc);
            Bs[lc + 0][row] = vb.x;
            Bs[lc + 1][row] = vb.y;
            Bs[lc + 2][row] = vb.z;
            Bs[lc + 3][row] = vb.w;
        }
        __syncthreads();

#pragma unroll
        for (int k = 0; k < GBK; k++) {
            float4 a0 = *(const float4*)&As[k][ty * 8];
            float4 a1 = *(const float4*)&As[k][ty * 8 + 4];
            float4 b0 = *(const float4*)&Bs[k][tx * 8];
            float4 b1 = *(const float4*)&Bs[k][tx * 8 + 4];
            float ra[8] = {a0.x, a0.y, a0.z, a0.w, a1.x, a1.y, a1.z, a1.w};
            float rb[8] = {b0.x, b0.y, b0.z, b0.w, b1.x, b1.y, b1.z, b1.w};
#pragma unroll
            for (int i = 0; i < 8; i++)
#pragma unroll
                for (int j = 0; j < 8; j++)
                    acc[i][j] += ra[i] * rb[j];
        }
        __syncthreads();
    }

#pragma unroll
    for (int i = 0; i < 8; i++) {
        const int row = blockIdx.y * GBM + ty * 8 + i;
#pragma unroll
        for (int j = 0; j < 8; j += 4) {
            const int col = blockIdx.x * GBN + tx * 8 + j;
            float4 o;
            o.x = acc[i][j + 0] + bias[col + 0];
            o.y = acc[i][j + 1] + bias[col + 1];
            o.z = acc[i][j + 2] + bias[col + 2];
            o.w = acc[i][j + 3] + bias[col + 3];
            *(float4*)(C + (size_t)row * N + col) = o;
        }
    }
}

// =================================================================
// Flash attention, fp32. One block = (64 q rows) x (one head) x (batch).
// 256 threads as 16x16; each thread owns a 4x4 fragment.
// Mask bias read as precomputed float (g_mbias).
// =================================================================
#define FP 65   // padded smem row stride (floats)

__global__ __launch_bounds__(256)
void flash_kernel(const float* __restrict__ Q, const float* __restrict__ K,
                  const float* __restrict__ V,
                  const float* __restrict__ mbias,
                  float* __restrict__ O) {
    extern __shared__ float sm[];
    float* Qs = sm;                 // 64*FP
    float* Ks = Qs + 64 * FP;       // 64*FP
    float* Vs = Ks + 64 * FP;       // 64*FP
    float* Ps = Vs + 64 * FP;       // 64*FP
    float* mb = Ps + 64 * FP;       // 64

    const int tid = threadIdx.x;
    const int tx = tid & 15;
    const int ty = tid >> 4;
    const int q0 = blockIdx.x * 64;
    const int h  = blockIdx.y;
    const int b  = blockIdx.z;

    const int r0 = ty * 4;   // q rows owned
    const int c0 = tx * 4;   // cols owned (key idx in pass1, head dim in pass2)

    // ---- load Q tile, pre-scaled by 1/sqrt(HD)=0.125 ----
    const float* Qg = Q + ((size_t)(b * S_ + q0)) * D_ + h * HD_;
    for (int idx = tid; idx < 64 * 16; idx += 256) {
        const int row = idx >> 4;
        const int c4  = (idx & 15) << 2;
        float4 v = *(const float4*)(Qg + (size_t)row * D_ + c4);
        Qs[row * FP + c4 + 0] = v.x * 0.125f;
        Qs[row * FP + c4 + 1] = v.y * 0.125f;
        Qs[row * FP + c4 + 2] = v.z * 0.125f;
        Qs[row * FP + c4 + 3] = v.w * 0.125f;
    }

    float acc[4][4] = {};
    float mrow[4], lrow[4];
#pragma unroll
    for (int i = 0; i < 4; i++) { mrow[i] = -1e29f; lrow[i] = 0.0f; }

    for (int kt = 0; kt < S_ / 64; kt++) {
        const float* Kg = K + ((size_t)(b * S_ + kt * 64)) * D_ + h * HD_;
        const float* Vg = V + ((size_t)(b * S_ + kt * 64)) * D_ + h * HD_;
        for (int idx = tid; idx < 64 * 16; idx += 256) {
            const int row = idx >> 4;
            const int c4  = (idx & 15) << 2;
            float4 v = *(const float4*)(Kg + (size_t)row * D_ + c4);
            Ks[row * FP + c4 + 0] = v.x;
            Ks[row * FP + c4 + 1] = v.y;
            Ks[row * FP + c4 + 2] = v.z;
            Ks[row * FP + c4 + 3] = v.w;
            float4 w = *(const float4*)(Vg + (size_t)row * D_ + c4);
            Vs[row * FP + c4 + 0] = w.x;
            Vs[row * FP + c4 + 1] = w.y;
            Vs[row * FP + c4 + 2] = w.z;
            Vs[row * FP + c4 + 3] = w.w;
        }
        if (tid < 64) {
            mb[tid] = mbias[b * S_ + kt * 64 + tid];
        }
        __syncthreads();

        // ---- S = Q K^T fragment ----
        float s[4][4] = {};
#pragma unroll 8
        for (int d = 0; d < HD_; d++) {
            float rq[4], rk[4];
#pragma unroll
            for (int i = 0; i < 4; i++) rq[i] = Qs[(r0 + i) * FP + d];
#pragma unroll
            for (int j = 0; j < 4; j++) rk[j] = Ks[(c0 + j) * FP + d];
#pragma unroll
            for (int i = 0; i < 4; i++)
#pragma unroll
                for (int j = 0; j < 4; j++)
                    s[i][j] += rq[i] * rk[j];
        }

        float mb4[4];
#pragma unroll
        for (int j = 0; j < 4; j++) mb4[j] = mb[c0 + j];

        // ---- online softmax update (rows owned by 16 threads of same ty) ----
#pragma unroll
        for (int i = 0; i < 4; i++) {
            float tmax = -3e38f;
#pragma unroll
            for (int j = 0; j < 4; j++) {
                s[i][j] += mb4[j];
                tmax = fmaxf(tmax, s[i][j]);
            }
#pragma unroll
            for (int o = 1; o < 16; o <<= 1)
                tmax = fmaxf(tmax, __shfl_xor_sync(0xffffffffu, tmax, o, 16));
            const float mnew = fmaxf(mrow[i], tmax);
            const float corr = __expf(mrow[i] - mnew);
            float ls = 0.0f;
#pragma unroll
            for (int j = 0; j < 4; j++) {
                const float p = __expf(s[i][j] - mnew);
                Ps[(r0 + i) * FP + c0 + j] = p;
                ls += p;
            }
#pragma unroll
            for (int o = 1; o < 16; o <<= 1)
                ls += __shfl_xor_sync(0xffffffffu, ls, o, 16);
            lrow[i] = lrow[i] * corr + ls;
            mrow[i] = mnew;
#pragma unroll
            for (int j = 0; j < 4; j++) acc[i][j] *= corr;
        }
        __syncthreads();

        // ---- O += P V ----
#pragma unroll 8
        for (int kk2 = 0; kk2 < 64; kk2++) {
            float rp[4], rv[4];
#pragma unroll
            for (int i = 0; i < 4; i++) rp[i] = Ps[(r0 + i) * FP + kk2];
#pragma unroll
            for (int j = 0; j < 4; j++) rv[j] = Vs[kk2 * FP + c0 + j];
#pragma unroll
            for (int i = 0; i < 4; i++)
#pragma unroll
                for (int j = 0; j < 4; j++)
                    acc[i][j] += rp[i] * rv[j];
        }
        __syncthreads();
    }

    float* Og = O + ((size_t)(b * S_ + q0)) * D_ + h * HD_;
#pragma unroll
    for (int i = 0; i < 4; i++) {
        const float inv = 1.0f / lrow[i];
#pragma unroll
        for (int j = 0; j < 4; j++)
            Og[(size_t)(r0 + i) * D_ + c0 + j] = acc[i][j] * inv;
    }
}

// =================================================================
// launch
// =================================================================
extern "C" void kernel_launch(void* const* d_in, const int* in_sizes, int n_in,
                              void* d_out, int out_size) {
    const float* query = (const float*)d_in[0];
    const float* key   = (const float*)d_in[1];
    const float* value = (const float*)d_in[2];
    const void*  kpm   = d_in[3];
    const void*  am    = d_in[4];
    // d_in[5] = is_casual (ignored: eval reference applies no causal mask)
    const float* Wq = (const float*)d_in[6];
    const float* bq = (const float*)d_in[7];
    const float* Wk = (const float*)d_in[8];
    const float* bk = (const float*)d_in[9];
    const float* Wv = (const float*)d_in[10];
    const float* bv = (const float*)d_in[11];
    const float* Wo = (const float*)d_in[12];
    const float* bo = (const float*)d_in[13];
    float* out = (float*)d_out;

    float *Qp, *Kp, *Vp, *X, *Mb;
    cudaGetSymbolAddress((void**)&Qp, g_Qp);
    cudaGetSymbolAddress((void**)&Kp, g_Kp);
    cudaGetSymbolAddress((void**)&Vp, g_Vp);
    cudaGetSymbolAddress((void**)&X,  g_X);
    cudaGetSymbolAddress((void**)&Mb, g_mbias);

    build_mask<<<1, 1024>>>(kpm, am, Mb);

    const dim3 gblk(256);
    const dim3 ggrid(D_ / GBN, NTOK / GBM);   // (8, 32)

    gemm_abt_bias<<<ggrid, gblk>>>(query, Wq, bq, Qp, NTOK, D_, D_);
    gemm_abt_bias<<<ggrid, gblk>>>(key,   Wk, bk, Kp, NTOK, D_, D_);
    gemm_abt_bias<<<ggrid, gblk>>>(value, Wv, bv, Vp, NTOK, D_, D_);

    const int fsmem = (4 * 64 * FP + 64) * (int)sizeof(float);  // ~66.8 KB
    cudaFuncSetAttribute(flash_kernel,
                         cudaFuncAttributeMaxDynamicSharedMemorySize, fsmem);
    flash_kernel<<<dim3(S_ / 64, H_, B_), 256, fsmem>>>(Qp, Kp, Vp, Mb, X);

    gemm_abt_bias<<<ggrid, gblk>>>(X, Wo, bo, out, NTOK, D_, D_);
}

// round 7
// speedup vs baseline: 1.3622x; 1.3622x over previous
#include <cuda_runtime.h>
#include <cuda_bf16.h>
#include <cstdint>

// Problem dims (fixed by reference)
#define B_   2
#define S_   2048
#define D_   1024
#define H_   16
#define HD_  64
#define NTOK (B_ * S_)   // 4096

// ---------------- scratch (no cudaMalloc allowed) ----------------
__device__ float g_Qp[(size_t)NTOK * D_];
__device__ float g_Kp[(size_t)NTOK * D_];
__device__ float g_Vp[(size_t)NTOK * D_];
__device__ float g_X [(size_t)NTOK * D_];
__device__ float g_mbias[NTOK];
__device__ __nv_bfloat16 g_Ahi[(size_t)NTOK * D_];
__device__ __nv_bfloat16 g_Alo[(size_t)NTOK * D_];
__device__ __nv_bfloat16 g_Whi[(size_t)D_ * D_];
__device__ __nv_bfloat16 g_Wlo[(size_t)D_ * D_];

// ================= helpers =================
__device__ __forceinline__ uint32_t smem_u32(const void* p) {
    uint32_t a;
    asm("{ .reg .u64 t; cvta.to.shared.u64 t, %1; cvt.u32.u64 %0, t; }"
        : "=r"(a) : "l"(p));
    return a;
}
#define SW128(o) ((o) ^ (((o) >> 3) & 0x70))

#define CP_ASYNC16(dst, src) \
    asm volatile("cp.async.cg.shared.global [%0], [%1], 16;" :: "r"(dst), "l"(src))
#define CP_COMMIT() asm volatile("cp.async.commit_group;" ::: "memory")
#define CP_WAIT(n)  asm volatile("cp.async.wait_group %0;" :: "n"(n) : "memory")

__device__ __forceinline__ void ldsm4(uint32_t* r, uint32_t addr) {
    asm volatile("ldmatrix.sync.aligned.m8n8.x4.shared.b16 {%0,%1,%2,%3}, [%4];"
                 : "=r"(r[0]), "=r"(r[1]), "=r"(r[2]), "=r"(r[3]) : "r"(addr));
}
__device__ __forceinline__ void mma_bf16(float* c, const uint32_t* a, const uint32_t* b) {
    asm volatile("mma.sync.aligned.m16n8k16.row.col.f32.bf16.bf16.f32 "
                 "{%0,%1,%2,%3}, {%4,%5,%6,%7}, {%8,%9}, {%0,%1,%2,%3};"
                 : "+f"(c[0]), "+f"(c[1]), "+f"(c[2]), "+f"(c[3])
                 : "r"(a[0]), "r"(a[1]), "r"(a[2]), "r"(a[3]),
                   "r"(b[0]), "r"(b[1]));
}

// =================================================================
// split fp32 -> bf16 hi + bf16 lo (x ~= hi + lo, err ~2^-17)
// =================================================================
__global__ void split_bf16(const float4* __restrict__ in,
                           __nv_bfloat162* __restrict__ hi,
                           __nv_bfloat162* __restrict__ lo, int n4) {
    int i = blockIdx.x * blockDim.x + threadIdx.x;
    if (i >= n4) return;
    float4 v = in[i];
    __nv_bfloat16 h0 = __float2bfloat16(v.x);
    __nv_bfloat16 h1 = __float2bfloat16(v.y);
    __nv_bfloat16 h2 = __float2bfloat16(v.z);
    __nv_bfloat16 h3 = __float2bfloat16(v.w);
    __nv_bfloat16 l0 = __float2bfloat16(v.x - __bfloat162float(h0));
    __nv_bfloat16 l1 = __float2bfloat16(v.y - __bfloat162float(h1));
    __nv_bfloat16 l2 = __float2bfloat16(v.z - __bfloat162float(h2));
    __nv_bfloat16 l3 = __float2bfloat16(v.w - __bfloat162float(h3));
    __nv_bfloat162 ph0; ph0.x = h0; ph0.y = h1;
    __nv_bfloat162 ph1; ph1.x = h2; ph1.y = h3;
    __nv_bfloat162 pl0; pl0.x = l0; pl0.y = l1;
    __nv_bfloat162 pl1; pl1.x = l2; pl1.y = l3;
    hi[2 * i + 0] = ph0;
    hi[2 * i + 1] = ph1;
    lo[2 * i + 0] = pl0;
    lo[2 * i + 1] = pl1;
}

// =================================================================
// Mask build (dtype auto-detect: packed uint8 vs int32)
// =================================================================
__global__ void build_mask(const void* __restrict__ kpm_raw,
                           const void* __restrict__ am_raw,
                           float* __restrict__ mb) {
    __shared__ int s_u8;
    if (threadIdx.x == 0) s_u8 = 0;
    __syncthreads();
    const int* probe = (const int*)kpm_raw;
    for (int i = threadIdx.x; i < 1024; i += blockDim.x)
        if ((unsigned)probe[i] > 1u) s_u8 = 1;
    __syncthreads();
    const int is_u8 = s_u8;
    for (int i = threadIdx.x; i < NTOK; i += blockDim.x) {
        int k, a;
        if (is_u8) {
            k = ((const uint8_t*)kpm_raw)[i];
            a = ((const uint8_t*)am_raw)[i];
        } else {
            k = ((const int*)kpm_raw)[i];
            a = ((const int*)am_raw)[i];
        }
        mb[i] = (k | a) ? -1e30f : 0.0f;
    }
}

// =================================================================
// mma.sync GEMM: C[m,n] = sum_k A[m,k]*W[n,k] + bias[n]
// A,W pre-split bf16 hi/lo; fp32 accum of Ah*Wh + Ah*Wl + Al*Wh.
// CTA 128x128, K-stage 64 (128B SW128 rows), 2-stage cp.async.
// 8 warps: warp tile 64x32 (wm = wid&1, wn = wid>>1).
// =================================================================
#define TILE_B  16384                 // 128 rows x 128 B
#define STG_B   (4 * TILE_B)          // Ah, Al, Wh, Wl
#define GSMEM   (2 * STG_B)           // 131072
#define KSTEPS  16

__global__ __launch_bounds__(256, 1)
void gemm_mma(const __nv_bfloat16* __restrict__ Ahi, const __nv_bfloat16* __restrict__ Alo,
              const __nv_bfloat16* __restrict__ Whi, const __nv_bfloat16* __restrict__ Wlo,
              const float* __restrict__ bias, float* __restrict__ C) {
    extern __shared__ char smem[];
    const uint32_t sb = smem_u32(smem);
    const int tid  = threadIdx.x;
    const int wid  = tid >> 5;
    const int lane = tid & 31;
    const int wm = wid & 1;      // 0..1 -> 64-row half
    const int wn = wid >> 1;     // 0..3 -> 32-col quarter

    const size_t aoff = (size_t)blockIdx.y * 128 * D_;
    const size_t woff = (size_t)blockIdx.x * 128 * D_;

    const __nv_bfloat16* srcs[4] = {Ahi + aoff, Alo + aoff, Whi + woff, Wlo + woff};

    // per-thread copy slots: chunk = tid + p*256; row = chunk>>3, c16 = chunk&7
    const int crow = tid >> 3;
    const int c16  = tid & 7;

    auto load_stage = [&](int ks, int stage) {
        const uint32_t stb = sb + stage * STG_B;
#pragma unroll
        for (int m = 0; m < 4; m++) {
            const __nv_bfloat16* g0 = srcs[m] + (size_t)ks * 64 + c16 * 8;
#pragma unroll
            for (int p = 0; p < 4; p++) {
                const int row = crow + p * 32;
                const uint32_t so = SW128((uint32_t)(row * 128 + c16 * 16));
                CP_ASYNC16(stb + m * TILE_B + so, g0 + (size_t)row * D_);
            }
        }
    };

    float acc[4][4][4] = {};

    load_stage(0, 0);
    CP_COMMIT();

    for (int ks = 0; ks < KSTEPS; ks++) {
        const int stage = ks & 1;
        if (ks + 1 < KSTEPS) {
            load_stage(ks + 1, stage ^ 1);
            CP_COMMIT();
            CP_WAIT(1);
        } else {
            CP_WAIT(0);
        }
        __syncthreads();

        const uint32_t sAh = sb + stage * STG_B;
        const uint32_t sAl = sAh + TILE_B;
        const uint32_t sWh = sAh + 2 * TILE_B;
        const uint32_t sWl = sAh + 3 * TILE_B;

#pragma unroll
        for (int kk = 0; kk < 4; kk++) {
            const uint32_t bcol = kk * 32 + ((lane >> 4) << 4);
            // ---- B fragments (hi/lo), 4 n8 frags each ----
            uint32_t bh[4][2], bl[4][2];
#pragma unroll
            for (int nb = 0; nb < 2; nb++) {
                const int row = wn * 32 + nb * 16 + (lane & 15);
                const uint32_t so = SW128((uint32_t)(row * 128) + bcol);
                uint32_t r4[4];
                ldsm4(r4, sWh + so);
                bh[2 * nb][0] = r4[0]; bh[2 * nb][1] = r4[2];
                bh[2 * nb + 1][0] = r4[1]; bh[2 * nb + 1][1] = r4[3];
                ldsm4(r4, sWl + so);
                bl[2 * nb][0] = r4[0]; bl[2 * nb][1] = r4[2];
                bl[2 * nb + 1][0] = r4[1]; bl[2 * nb + 1][1] = r4[3];
            }
#pragma unroll
            for (int mf = 0; mf < 4; mf++) {
                const int row = wm * 64 + mf * 16 + (lane & 15);
                const uint32_t so = SW128((uint32_t)(row * 128) + bcol);
                uint32_t ah[4], al[4];
                ldsm4(ah, sAh + so);
                ldsm4(al, sAl + so);
#pragma unroll
                for (int nf = 0; nf < 4; nf++) {
                    mma_bf16(acc[mf][nf], ah, bh[nf]);
                    mma_bf16(acc[mf][nf], ah, bl[nf]);
                    mma_bf16(acc[mf][nf], al, bh[nf]);
                }
            }
        }
        __syncthreads();
    }

    // ---- epilogue ----
    const int r  = lane >> 2;
    const int c2 = (lane & 3) * 2;
#pragma unroll
    for (int nf = 0; nf < 4; nf++) {
        const int gcol = blockIdx.x * 128 + wn * 32 + nf * 8 + c2;
        const float b0 = __ldg(bias + gcol);
        const float b1 = __ldg(bias + gcol + 1);
#pragma unroll
        for (int mf = 0; mf < 4; mf++) {
            const int grow = blockIdx.y * 128 + wm * 64 + mf * 16 + r;
            float2 v0 = {acc[mf][nf][0] + b0, acc[mf][nf][1] + b1};
            float2 v1 = {acc[mf][nf][2] + b0, acc[mf][nf][3] + b1};
            *(float2*)(C + (size_t)grow * D_ + gcol) = v0;
            *(float2*)(C + (size_t)(grow + 8) * D_ + gcol) = v1;
        }
    }
}

// =================================================================
// Flash attention, fp32 (passing version from R2).
// =================================================================
#define FP 65

__global__ __launch_bounds__(256)
void flash_kernel(const float* __restrict__ Q, const float* __restrict__ K,
                  const float* __restrict__ V,
                  const float* __restrict__ mbias,
                  float* __restrict__ O) {
    extern __shared__ float sm[];
    float* Qs = sm;
    float* Ks = Qs + 64 * FP;
    float* Vs = Ks + 64 * FP;
    float* Ps = Vs + 64 * FP;
    float* mb = Ps + 64 * FP;

    const int tid = threadIdx.x;
    const int tx = tid & 15;
    const int ty = tid >> 4;
    const int q0 = blockIdx.x * 64;
    const int h  = blockIdx.y;
    const int b  = blockIdx.z;

    const int r0 = ty * 4;
    const int c0 = tx * 4;

    const float* Qg = Q + ((size_t)(b * S_ + q0)) * D_ + h * HD_;
    for (int idx = tid; idx < 64 * 16; idx += 256) {
        const int row = idx >> 4;
        const int c4  = (idx & 15) << 2;
        float4 v = *(const float4*)(Qg + (size_t)row * D_ + c4);
        Qs[row * FP + c4 + 0] = v.x * 0.125f;
        Qs[row * FP + c4 + 1] = v.y * 0.125f;
        Qs[row * FP + c4 + 2] = v.z * 0.125f;
        Qs[row * FP + c4 + 3] = v.w * 0.125f;
    }

    float acc[4][4] = {};
    float mrow[4], lrow[4];
#pragma unroll
    for (int i = 0; i < 4; i++) { mrow[i] = -1e29f; lrow[i] = 0.0f; }

    for (int kt = 0; kt < S_ / 64; kt++) {
        const float* Kg = K + ((size_t)(b * S_ + kt * 64)) * D_ + h * HD_;
        const float* Vg = V + ((size_t)(b * S_ + kt * 64)) * D_ + h * HD_;
        for (int idx = tid; idx < 64 * 16; idx += 256) {
            const int row = idx >> 4;
            const int c4  = (idx & 15) << 2;
            float4 v = *(const float4*)(Kg + (size_t)row * D_ + c4);
            Ks[row * FP + c4 + 0] = v.x;
            Ks[row * FP + c4 + 1] = v.y;
            Ks[row * FP + c4 + 2] = v.z;
            Ks[row * FP + c4 + 3] = v.w;
            float4 w = *(const float4*)(Vg + (size_t)row * D_ + c4);
            Vs[row * FP + c4 + 0] = w.x;
            Vs[row * FP + c4 + 1] = w.y;
            Vs[row * FP + c4 + 2] = w.z;
            Vs[row * FP + c4 + 3] = w.w;
        }
        if (tid < 64) {
            mb[tid] = mbias[b * S_ + kt * 64 + tid];
        }
        __syncthreads();

        float s[4][4] = {};
#pragma unroll 8
        for (int d = 0; d < HD_; d++) {
            float rq[4], rk[4];
#pragma unroll
            for (int i = 0; i < 4; i++) rq[i] = Qs[(r0 + i) * FP + d];
#pragma unroll
            for (int j = 0; j < 4; j++) rk[j] = Ks[(c0 + j) * FP + d];
#pragma unroll
            for (int i = 0; i < 4; i++)
#pragma unroll
                for (int j = 0; j < 4; j++)
                    s[i][j] += rq[i] * rk[j];
        }

        float mb4[4];
#pragma unroll
        for (int j = 0; j < 4; j++) mb4[j] = mb[c0 + j];

#pragma unroll
        for (int i = 0; i < 4; i++) {
            float tmax = -3e38f;
#pragma unroll
            for (int j = 0; j < 4; j++) {
                s[i][j] += mb4[j];
                tmax = fmaxf(tmax, s[i][j]);
            }
#pragma unroll
            for (int o = 1; o < 16; o <<= 1)
                tmax = fmaxf(tmax, __shfl_xor_sync(0xffffffffu, tmax, o, 16));
            const float mnew = fmaxf(mrow[i], tmax);
            const float corr = __expf(mrow[i] - mnew);
            float ls = 0.0f;
#pragma unroll
            for (int j = 0; j < 4; j++) {
                const float p = __expf(s[i][j] - mnew);
                Ps[(r0 + i) * FP + c0 + j] = p;
                ls += p;
            }
#pragma unroll
            for (int o = 1; o < 16; o <<= 1)
                ls += __shfl_xor_sync(0xffffffffu, ls, o, 16);
            lrow[i] = lrow[i] * corr + ls;
            mrow[i] = mnew;
#pragma unroll
            for (int j = 0; j < 4; j++) acc[i][j] *= corr;
        }
        __syncthreads();

#pragma unroll 8
        for (int kk2 = 0; kk2 < 64; kk2++) {
            float rp[4], rv[4];
#pragma unroll
            for (int i = 0; i < 4; i++) rp[i] = Ps[(r0 + i) * FP + kk2];
#pragma unroll
            for (int j = 0; j < 4; j++) rv[j] = Vs[kk2 * FP + c0 + j];
#pragma unroll
            for (int i = 0; i < 4; i++)
#pragma unroll
                for (int j = 0; j < 4; j++)
                    acc[i][j] += rp[i] * rv[j];
        }
        __syncthreads();
    }

    float* Og = O + ((size_t)(b * S_ + q0)) * D_ + h * HD_;
#pragma unroll
    for (int i = 0; i < 4; i++) {
        const float inv = 1.0f / lrow[i];
#pragma unroll
        for (int j = 0; j < 4; j++)
            Og[(size_t)(r0 + i) * D_ + c0 + j] = acc[i][j] * inv;
    }
}

// =================================================================
// launch
// =================================================================
extern "C" void kernel_launch(void* const* d_in, const int* in_sizes, int n_in,
                              void* d_out, int out_size) {
    const float* query = (const float*)d_in[0];
    const float* key   = (const float*)d_in[1];
    const float* value = (const float*)d_in[2];
    const void*  kpm   = d_in[3];
    const void*  am    = d_in[4];
    // d_in[5] = is_casual (ignored in eval mode)
    const float* Wq = (const float*)d_in[6];
    const float* bq = (const float*)d_in[7];
    const float* Wk = (const float*)d_in[8];
    const float* bk = (const float*)d_in[9];
    const float* Wv = (const float*)d_in[10];
    const float* bv = (const float*)d_in[11];
    const float* Wo = (const float*)d_in[12];
    const float* bo = (const float*)d_in[13];
    float* out = (float*)d_out;

    float *Qp, *Kp, *Vp, *X, *Mb;
    __nv_bfloat16 *Ahi, *Alo, *Whi, *Wlo;
    cudaGetSymbolAddress((void**)&Qp, g_Qp);
    cudaGetSymbolAddress((void**)&Kp, g_Kp);
    cudaGetSymbolAddress((void**)&Vp, g_Vp);
    cudaGetSymbolAddress((void**)&X,  g_X);
    cudaGetSymbolAddress((void**)&Mb, g_mbias);
    cudaGetSymbolAddress((void**)&Ahi, g_Ahi);
    cudaGetSymbolAddress((void**)&Alo, g_Alo);
    cudaGetSymbolAddress((void**)&Whi, g_Whi);
    cudaGetSymbolAddress((void**)&Wlo, g_Wlo);

    build_mask<<<1, 1024>>>(kpm, am, Mb);

    cudaFuncSetAttribute(gemm_mma, cudaFuncAttributeMaxDynamicSharedMemorySize, GSMEM);

    const int nA4 = NTOK * D_ / 4;   // 1M
    const int nW4 = D_ * D_ / 4;     // 256K
    const dim3 ggrid(D_ / 128, NTOK / 128);  // (8, 32)

    struct { const float* A; const float* W; const float* b; float* C; }
    gemms[4] = {
        {query, Wq, bq, Qp},
        {key,   Wk, bk, Kp},
        {value, Wv, bv, Vp},
        {X,     Wo, bo, out},
    };

    for (int g = 0; g < 4; g++) {
        if (g == 3) {
            const int fsmem = (4 * 64 * FP + 64) * (int)sizeof(float);
            cudaFuncSetAttribute(flash_kernel,
                                 cudaFuncAttributeMaxDynamicSharedMemorySize, fsmem);
            flash_kernel<<<dim3(S_ / 64, H_, B_), 256, fsmem>>>(Qp, Kp, Vp, Mb, X);
        }
        split_bf16<<<(nA4 + 255) / 256, 256>>>((const float4*)gemms[g].A,
                                               (__nv_bfloat162*)Ahi, (__nv_bfloat162*)Alo, nA4);
        split_bf16<<<(nW4 + 255) / 256, 256>>>((const float4*)gemms[g].W,
                                               (__nv_bfloat162*)Whi, (__nv_bfloat162*)Wlo, nW4);
        gemm_mma<<<ggrid, 256, GSMEM>>>(Ahi, Alo, Whi, Wlo, gemms[g].b, gemms[g].C);
    }
}

// round 8
// speedup vs baseline: 2.4001x; 1.7619x over previous
#include <cuda_runtime.h>
#include <cuda_bf16.h>
#include <cuda_fp16.h>
#include <cstdint>

// Problem dims (fixed by reference)
#define B_   2
#define S_   2048
#define D_   1024
#define H_   16
#define HD_  64
#define NTOK (B_ * S_)   // 4096

// ---------------- scratch (no cudaMalloc allowed) ----------------
__device__ float g_Qp[(size_t)NTOK * D_];
__device__ float g_Kp[(size_t)NTOK * D_];
__device__ float g_Vp[(size_t)NTOK * D_];
__device__ float g_X [(size_t)NTOK * D_];
__device__ float g_mbias[NTOK];
__device__ __nv_bfloat16 g_Ahi[(size_t)NTOK * D_];
__device__ __nv_bfloat16 g_Alo[(size_t)NTOK * D_];
__device__ __nv_bfloat16 g_Whi[(size_t)D_ * D_];
__device__ __nv_bfloat16 g_Wlo[(size_t)D_ * D_];
__device__ __half g_Qh[(size_t)NTOK * D_];
__device__ __half g_Kh[(size_t)NTOK * D_];
__device__ __half g_Vt[(size_t)NTOK * D_];   // [B,H,HD,S] transposed per head

// ================= helpers =================
__device__ __forceinline__ uint32_t smem_u32(const void* p) {
    uint32_t a;
    asm("{ .reg .u64 t; cvta.to.shared.u64 t, %1; cvt.u32.u64 %0, t; }"
        : "=r"(a) : "l"(p));
    return a;
}
#define SW128(o) ((o) ^ (((o) >> 3) & 0x70))

#define CP_ASYNC16(dst, src) \
    asm volatile("cp.async.cg.shared.global [%0], [%1], 16;" :: "r"(dst), "l"(src))
#define CP_COMMIT() asm volatile("cp.async.commit_group;" ::: "memory")
#define CP_WAIT(n)  asm volatile("cp.async.wait_group %0;" :: "n"(n) : "memory")

__device__ __forceinline__ void ldsm4(uint32_t* r, uint32_t addr) {
    asm volatile("ldmatrix.sync.aligned.m8n8.x4.shared.b16 {%0,%1,%2,%3}, [%4];"
                 : "=r"(r[0]), "=r"(r[1]), "=r"(r[2]), "=r"(r[3]) : "r"(addr));
}
__device__ __forceinline__ void mma_bf16(float* c, const uint32_t* a, const uint32_t* b) {
    asm volatile("mma.sync.aligned.m16n8k16.row.col.f32.bf16.bf16.f32 "
                 "{%0,%1,%2,%3}, {%4,%5,%6,%7}, {%8,%9}, {%0,%1,%2,%3};"
                 : "+f"(c[0]), "+f"(c[1]), "+f"(c[2]), "+f"(c[3])
                 : "r"(a[0]), "r"(a[1]), "r"(a[2]), "r"(a[3]),
                   "r"(b[0]), "r"(b[1]));
}
__device__ __forceinline__ void mma_f16(float* c, const uint32_t* a, const uint32_t* b) {
    asm volatile("mma.sync.aligned.m16n8k16.row.col.f32.f16.f16.f32 "
                 "{%0,%1,%2,%3}, {%4,%5,%6,%7}, {%8,%9}, {%0,%1,%2,%3};"
                 : "+f"(c[0]), "+f"(c[1]), "+f"(c[2]), "+f"(c[3])
                 : "r"(a[0]), "r"(a[1]), "r"(a[2]), "r"(a[3]),
                   "r"(b[0]), "r"(b[1]));
}
__device__ __forceinline__ uint32_t pack_f16x2(float lo, float hi) {
    uint32_t d;
    asm("cvt.rn.f16x2.f32 %0, %1, %2;" : "=r"(d) : "f"(hi), "f"(lo));
    return d;
}

// =================================================================
// split fp32 -> bf16 hi + bf16 lo
// =================================================================
__global__ void split_bf16(const float4* __restrict__ in,
                           __nv_bfloat162* __restrict__ hi,
                           __nv_bfloat162* __restrict__ lo, int n4) {
    int i = blockIdx.x * blockDim.x + threadIdx.x;
    if (i >= n4) return;
    float4 v = in[i];
    __nv_bfloat16 h0 = __float2bfloat16(v.x);
    __nv_bfloat16 h1 = __float2bfloat16(v.y);
    __nv_bfloat16 h2 = __float2bfloat16(v.z);
    __nv_bfloat16 h3 = __float2bfloat16(v.w);
    __nv_bfloat16 l0 = __float2bfloat16(v.x - __bfloat162float(h0));
    __nv_bfloat16 l1 = __float2bfloat16(v.y - __bfloat162float(h1));
    __nv_bfloat16 l2 = __float2bfloat16(v.z - __bfloat162float(h2));
    __nv_bfloat16 l3 = __float2bfloat16(v.w - __bfloat162float(h3));
    __nv_bfloat162 ph0; ph0.x = h0; ph0.y = h1;
    __nv_bfloat162 ph1; ph1.x = h2; ph1.y = h3;
    __nv_bfloat162 pl0; pl0.x = l0; pl0.y = l1;
    __nv_bfloat162 pl1; pl1.x = l2; pl1.y = l3;
    hi[2 * i + 0] = ph0;
    hi[2 * i + 1] = ph1;
    lo[2 * i + 0] = pl0;
    lo[2 * i + 1] = pl1;
}

// fp32 -> fp16 with scale
__global__ void conv_f16(const float4* __restrict__ in, __half2* __restrict__ out,
                         float scale, int n4) {
    int i = blockIdx.x * blockDim.x + threadIdx.x;
    if (i >= n4) return;
    float4 v = in[i];
    out[2 * i + 0] = __floats2half2_rn(v.x * scale, v.y * scale);
    out[2 * i + 1] = __floats2half2_rn(v.z * scale, v.w * scale);
}

// V fp32 [b*S+s][h*64+d] -> fp16 [ (bh*64+d) * S + s ]  (per-head transpose)
__global__ void conv_vt(const float* __restrict__ V, __half* __restrict__ Vt) {
    __shared__ float tile[32][33];
    const int s0 = blockIdx.x * 32;
    const int d0 = blockIdx.y * 32;
    const int bh = blockIdx.z;
    const int b = bh >> 4, h = bh & 15;
    const int tx = threadIdx.x, ty = threadIdx.y;
#pragma unroll
    for (int i = 0; i < 4; i++) {
        const int s = s0 + ty + i * 8;
        tile[ty + i * 8][tx] = V[(size_t)(b * S_ + s) * D_ + h * HD_ + d0 + tx];
    }
    __syncthreads();
#pragma unroll
    for (int i = 0; i < 4; i++) {
        const int d = d0 + ty + i * 8;
        Vt[(size_t)(bh * HD_ + d) * S_ + s0 + tx] = __float2half(tile[tx][ty + i * 8]);
    }
}

// =================================================================
// Mask build (dtype auto-detect: packed uint8 vs int32)
// =================================================================
__global__ void build_mask(const void* __restrict__ kpm_raw,
                           const void* __restrict__ am_raw,
                           float* __restrict__ mb) {
    __shared__ int s_u8;
    if (threadIdx.x == 0) s_u8 = 0;
    __syncthreads();
    const int* probe = (const int*)kpm_raw;
    for (int i = threadIdx.x; i < 1024; i += blockDim.x)
        if ((unsigned)probe[i] > 1u) s_u8 = 1;
    __syncthreads();
    const int is_u8 = s_u8;
    for (int i = threadIdx.x; i < NTOK; i += blockDim.x) {
        int k, a;
        if (is_u8) {
            k = ((const uint8_t*)kpm_raw)[i];
            a = ((const uint8_t*)am_raw)[i];
        } else {
            k = ((const int*)kpm_raw)[i];
            a = ((const int*)am_raw)[i];
        }
        mb[i] = (k | a) ? -1e30f : 0.0f;
    }
}

// =================================================================
// mma.sync GEMM (unchanged, passing @85us): C = A*W^T + bias, bf16x3 split
// =================================================================
#define TILE_B  16384
#define STG_B   (4 * TILE_B)
#define GSMEM   (2 * STG_B)
#define KSTEPS  16

__global__ __launch_bounds__(256, 1)
void gemm_mma(const __nv_bfloat16* __restrict__ Ahi, const __nv_bfloat16* __restrict__ Alo,
              const __nv_bfloat16* __restrict__ Whi, const __nv_bfloat16* __restrict__ Wlo,
              const float* __restrict__ bias, float* __restrict__ C) {
    extern __shared__ char smem[];
    const uint32_t sb = smem_u32(smem);
    const int tid  = threadIdx.x;
    const int wid  = tid >> 5;
    const int lane = tid & 31;
    const int wm = wid & 1;
    const int wn = wid >> 1;

    const size_t aoff = (size_t)blockIdx.y * 128 * D_;
    const size_t woff = (size_t)blockIdx.x * 128 * D_;
    const __nv_bfloat16* srcs[4] = {Ahi + aoff, Alo + aoff, Whi + woff, Wlo + woff};

    const int crow = tid >> 3;
    const int c16  = tid & 7;

    auto load_stage = [&](int ks, int stage) {
        const uint32_t stb = sb + stage * STG_B;
#pragma unroll
        for (int m = 0; m < 4; m++) {
            const __nv_bfloat16* g0 = srcs[m] + (size_t)ks * 64 + c16 * 8;
#pragma unroll
            for (int p = 0; p < 4; p++) {
                const int row = crow + p * 32;
                const uint32_t so = SW128((uint32_t)(row * 128 + c16 * 16));
                CP_ASYNC16(stb + m * TILE_B + so, g0 + (size_t)row * D_);
            }
        }
    };

    float acc[4][4][4] = {};
    load_stage(0, 0);
    CP_COMMIT();

    for (int ks = 0; ks < KSTEPS; ks++) {
        const int stage = ks & 1;
        if (ks + 1 < KSTEPS) {
            load_stage(ks + 1, stage ^ 1);
            CP_COMMIT();
            CP_WAIT(1);
        } else {
            CP_WAIT(0);
        }
        __syncthreads();

        const uint32_t sAh = sb + stage * STG_B;
        const uint32_t sAl = sAh + TILE_B;
        const uint32_t sWh = sAh + 2 * TILE_B;
        const uint32_t sWl = sAh + 3 * TILE_B;

#pragma unroll
        for (int kk = 0; kk < 4; kk++) {
            const uint32_t bcol = kk * 32 + ((lane >> 4) << 4);
            uint32_t bh[4][2], bl[4][2];
#pragma unroll
            for (int nb = 0; nb < 2; nb++) {
                const int row = wn * 32 + nb * 16 + (lane & 15);
                const uint32_t so = SW128((uint32_t)(row * 128) + bcol);
                uint32_t r4[4];
                ldsm4(r4, sWh + so);
                bh[2 * nb][0] = r4[0]; bh[2 * nb][1] = r4[2];
                bh[2 * nb + 1][0] = r4[1]; bh[2 * nb + 1][1] = r4[3];
                ldsm4(r4, sWl + so);
                bl[2 * nb][0] = r4[0]; bl[2 * nb][1] = r4[2];
                bl[2 * nb + 1][0] = r4[1]; bl[2 * nb + 1][1] = r4[3];
            }
#pragma unroll
            for (int mf = 0; mf < 4; mf++) {
                const int row = wm * 64 + mf * 16 + (lane & 15);
                const uint32_t so = SW128((uint32_t)(row * 128) + bcol);
                uint32_t ah[4], al[4];
                ldsm4(ah, sAh + so);
                ldsm4(al, sAl + so);
#pragma unroll
                for (int nf = 0; nf < 4; nf++) {
                    mma_bf16(acc[mf][nf], ah, bh[nf]);
                    mma_bf16(acc[mf][nf], ah, bl[nf]);
                    mma_bf16(acc[mf][nf], al, bh[nf]);
                }
            }
        }
        __syncthreads();
    }

    const int r  = lane >> 2;
    const int c2 = (lane & 3) * 2;
#pragma unroll
    for (int nf = 0; nf < 4; nf++) {
        const int gcol = blockIdx.x * 128 + wn * 32 + nf * 8 + c2;
        const float b0 = __ldg(bias + gcol);
        const float b1 = __ldg(bias + gcol + 1);
#pragma unroll
        for (int mf = 0; mf < 4; mf++) {
            const int grow = blockIdx.y * 128 + wm * 64 + mf * 16 + r;
            float2 v0 = {acc[mf][nf][0] + b0, acc[mf][nf][1] + b1};
            float2 v1 = {acc[mf][nf][2] + b0, acc[mf][nf][3] + b1};
            *(float2*)(C + (size_t)grow * D_ + gcol) = v0;
            *(float2*)(C + (size_t)(grow + 8) * D_ + gcol) = v1;
        }
    }
}

// =================================================================
// Flash attention, fp16 mma. CTA = 128 q-rows x one (b,h).
// 8 warps x 16 q-rows. k-tiles of 64, double-buffered cp.async.
// Q pre-scaled by 0.125 (folded into conv_f16). V pre-transposed.
// QK C-frags reused as PV A-frags (f32->f16x2 pack).
// =================================================================
#define FSQ   0
#define FSK   16384
#define FSV   (16384 + 16384)
#define FSMB  (FSV + 16384)
#define FSMEM (FSMB + 512)
#define NKT   (S_ / 64)

__global__ __launch_bounds__(256, 1)
void flash_mma(const __half* __restrict__ Qh, const __half* __restrict__ Kh,
               const __half* __restrict__ Vt, const float* __restrict__ mbias,
               float* __restrict__ O) {
    extern __shared__ char smem[];
    const uint32_t sb = smem_u32(smem);
    const int tid  = threadIdx.x;
    const int wid  = tid >> 5;
    const int lane = tid & 31;
    const int q0 = blockIdx.x * 128;
    const int h  = blockIdx.y;
    const int b  = blockIdx.z;

    const int crow = tid >> 3;     // 0..31 (loader row)
    const int c16  = tid & 7;      // 16B chunk

    const __half* Qg = Qh + (size_t)(b * S_ + q0) * D_ + h * HD_;
    const __half* Kg = Kh + (size_t)b * S_ * D_ + h * HD_;
    const __half* Vg = Vt + (size_t)(b * H_ + h) * HD_ * S_;
    const float*  Mg = mbias + b * S_;

    // ---- initial loads: Q (128x64) + stage 0 of K/V/mask ----
#pragma unroll
    for (int p = 0; p < 4; p++) {
        const int row = crow + p * 32;
        CP_ASYNC16(sb + FSQ + SW128((uint32_t)(row * 128 + c16 * 16)),
                   Qg + (size_t)row * D_ + c16 * 8);
    }
    auto load_stage = [&](int kt, int st) {
#pragma unroll
        for (int p = 0; p < 2; p++) {
            const int row = crow + p * 32;       // 0..63
            const uint32_t so = SW128((uint32_t)(row * 128 + c16 * 16));
            CP_ASYNC16(sb + FSK + st * 8192 + so,
                       Kg + (size_t)(kt * 64 + row) * D_ + c16 * 8);
            CP_ASYNC16(sb + FSV + st * 8192 + so,
                       Vg + (size_t)row * S_ + kt * 64 + c16 * 8);
        }
        if (tid < 16)
            CP_ASYNC16(sb + FSMB + st * 256 + tid * 16, Mg + kt * 64 + tid * 4);
    };
    load_stage(0, 0);
    CP_COMMIT();

    uint32_t qf[4][4];
    float o[8][4] = {};
    float m0 = -1e30f, m1 = -1e30f, l0 = 0.0f, l1 = 0.0f;

    const int lrow = lane & 15;
    const uint32_t lcol = (uint32_t)((lane >> 4) << 4);

    for (int kt = 0; kt < NKT; kt++) {
        const int st = kt & 1;
        if (kt + 1 < NKT) {
            load_stage(kt + 1, st ^ 1);
            CP_COMMIT();
            CP_WAIT(1);
        } else {
            CP_WAIT(0);
        }
        __syncthreads();

        if (kt == 0) {
            // Q fragments, register-resident for the whole kernel
#pragma unroll
            for (int ks = 0; ks < 4; ks++)
                ldsm4(qf[ks], sb + FSQ +
                      SW128((uint32_t)((wid * 16 + lrow) * 128 + ks * 32) + lcol));
        }

        const uint32_t sbK = sb + FSK + st * 8192;
        const uint32_t sbV = sb + FSV + st * 8192;
        const float* mbp = (const float*)(smem + FSMB + st * 256);

        // ---- S = Q K^T ----
        float s[8][4] = {};
#pragma unroll
        for (int ks = 0; ks < 4; ks++) {
#pragma unroll
            for (int nb = 0; nb < 4; nb++) {
                uint32_t r4[4];
                ldsm4(r4, sbK + SW128((uint32_t)((nb * 16 + lrow) * 128 + ks * 32) + lcol));
                uint32_t b0[2] = {r4[0], r4[2]};
                uint32_t b1[2] = {r4[1], r4[3]};
                mma_f16(s[2 * nb], qf[ks], b0);
                mma_f16(s[2 * nb + 1], qf[ks], b1);
            }
        }

        // ---- mask + online softmax ----
        const int cbase = (lane & 3) * 2;
        float tm0 = -3e38f, tm1 = -3e38f;
#pragma unroll
        for (int nf = 0; nf < 8; nf++) {
            float2 mv = *(const float2*)(mbp + nf * 8 + cbase);
            s[nf][0] += mv.x; s[nf][1] += mv.y;
            s[nf][2] += mv.x; s[nf][3] += mv.y;
            tm0 = fmaxf(tm0, fmaxf(s[nf][0], s[nf][1]));
            tm1 = fmaxf(tm1, fmaxf(s[nf][2], s[nf][3]));
        }
        tm0 = fmaxf(tm0, __shfl_xor_sync(0xffffffffu, tm0, 1));
        tm0 = fmaxf(tm0, __shfl_xor_sync(0xffffffffu, tm0, 2));
        tm1 = fmaxf(tm1, __shfl_xor_sync(0xffffffffu, tm1, 1));
        tm1 = fmaxf(tm1, __shfl_xor_sync(0xffffffffu, tm1, 2));

        const float mn0 = fmaxf(m0, tm0);
        const float mn1 = fmaxf(m1, tm1);
        const float cr0 = __expf(m0 - mn0);
        const float cr1 = __expf(m1 - mn1);
        m0 = mn0; m1 = mn1;

        uint32_t pa[4][4];
        float ls0 = 0.0f, ls1 = 0.0f;
#pragma unroll
        for (int nf = 0; nf < 8; nf++) {
            float p0 = __expf(s[nf][0] - m0);
            float p1 = __expf(s[nf][1] - m0);
            float p2 = __expf(s[nf][2] - m1);
            float p3 = __expf(s[nf][3] - m1);
            ls0 += p0 + p1;
            ls1 += p2 + p3;
            const int kk = nf >> 1;
            if ((nf & 1) == 0) {
                pa[kk][0] = pack_f16x2(p0, p1);
                pa[kk][1] = pack_f16x2(p2, p3);
            } else {
                pa[kk][2] = pack_f16x2(p0, p1);
                pa[kk][3] = pack_f16x2(p2, p3);
            }
        }
        ls0 += __shfl_xor_sync(0xffffffffu, ls0, 1);
        ls0 += __shfl_xor_sync(0xffffffffu, ls0, 2);
        ls1 += __shfl_xor_sync(0xffffffffu, ls1, 1);
        ls1 += __shfl_xor_sync(0xffffffffu, ls1, 2);
        l0 = l0 * cr0 + ls0;
        l1 = l1 * cr1 + ls1;
#pragma unroll
        for (int nf = 0; nf < 8; nf++) {
            o[nf][0] *= cr0; o[nf][1] *= cr0;
            o[nf][2] *= cr1; o[nf][3] *= cr1;
        }

        // ---- O += P V  (V transposed: rows=d, cols=key) ----
#pragma unroll
        for (int kk = 0; kk < 4; kk++) {
#pragma unroll
            for (int nb = 0; nb < 4; nb++) {
                uint32_t r4[4];
                ldsm4(r4, sbV + SW128((uint32_t)((nb * 16 + lrow) * 128 + kk * 32) + lcol));
                uint32_t b0[2] = {r4[0], r4[2]};
                uint32_t b1[2] = {r4[1], r4[3]};
                mma_f16(o[2 * nb], pa[kk], b0);
                mma_f16(o[2 * nb + 1], pa[kk], b1);
            }
        }
        __syncthreads();
    }

    // ---- write O ----
    const float inv0 = 1.0f / l0;
    const float inv1 = 1.0f / l1;
    const int r = lane >> 2;
    const int tok0 = b * S_ + q0 + wid * 16 + r;
#pragma unroll
    for (int nf = 0; nf < 8; nf++) {
        const int col = h * HD_ + nf * 8 + (lane & 3) * 2;
        float2 v0 = {o[nf][0] * inv0, o[nf][1] * inv0};
        float2 v1 = {o[nf][2] * inv1, o[nf][3] * inv1};
        *(float2*)(O + (size_t)tok0 * D_ + col) = v0;
        *(float2*)(O + (size_t)(tok0 + 8) * D_ + col) = v1;
    }
}

// =================================================================
// launch
// =================================================================
extern "C" void kernel_launch(void* const* d_in, const int* in_sizes, int n_in,
                              void* d_out, int out_size) {
    const float* query = (const float*)d_in[0];
    const float* key   = (const float*)d_in[1];
    const float* value = (const float*)d_in[2];
    const void*  kpm   = d_in[3];
    const void*  am    = d_in[4];
    // d_in[5] = is_casual (ignored in eval mode)
    const float* Wq = (const float*)d_in[6];
    const float* bq = (const float*)d_in[7];
    const float* Wk = (const float*)d_in[8];
    const float* bk = (const float*)d_in[9];
    const float* Wv = (const float*)d_in[10];
    const float* bv = (const float*)d_in[11];
    const float* Wo = (const float*)d_in[12];
    const float* bo = (const float*)d_in[13];
    float* out = (float*)d_out;

    float *Qp, *Kp, *Vp, *X, *Mb;
    __nv_bfloat16 *Ahi, *Alo, *Whi, *Wlo;
    __half *Qh, *Kh, *Vt;
    cudaGetSymbolAddress((void**)&Qp, g_Qp);
    cudaGetSymbolAddress((void**)&Kp, g_Kp);
    cudaGetSymbolAddress((void**)&Vp, g_Vp);
    cudaGetSymbolAddress((void**)&X,  g_X);
    cudaGetSymbolAddress((void**)&Mb, g_mbias);
    cudaGetSymbolAddress((void**)&Ahi, g_Ahi);
    cudaGetSymbolAddress((void**)&Alo, g_Alo);
    cudaGetSymbolAddress((void**)&Whi, g_Whi);
    cudaGetSymbolAddress((void**)&Wlo, g_Wlo);
    cudaGetSymbolAddress((void**)&Qh, g_Qh);
    cudaGetSymbolAddress((void**)&Kh, g_Kh);
    cudaGetSymbolAddress((void**)&Vt, g_Vt);

    build_mask<<<1, 1024>>>(kpm, am, Mb);

    cudaFuncSetAttribute(gemm_mma, cudaFuncAttributeMaxDynamicSharedMemorySize, GSMEM);
    cudaFuncSetAttribute(flash_mma, cudaFuncAttributeMaxDynamicSharedMemorySize, FSMEM);

    const int nA4 = NTOK * D_ / 4;
    const int nW4 = D_ * D_ / 4;
    const dim3 ggrid(D_ / 128, NTOK / 128);

    struct { const float* A; const float* W; const float* b; float* C; }
    gemms[4] = {
        {query, Wq, bq, Qp},
        {key,   Wk, bk, Kp},
        {value, Wv, bv, Vp},
        {X,     Wo, bo, out},
    };

    for (int g = 0; g < 4; g++) {
        if (g == 3) {
            // converts + flash before the output projection
            conv_f16<<<(nA4 + 255) / 256, 256>>>((const float4*)Qp, (__half2*)Qh, 0.125f, nA4);
            conv_f16<<<(nA4 + 255) / 256, 256>>>((const float4*)Kp, (__half2*)Kh, 1.0f, nA4);
            conv_vt<<<dim3(S_ / 32, HD_ / 32, B_ * H_), dim3(32, 8)>>>(Vp, Vt);
            flash_mma<<<dim3(S_ / 128, H_, B_), 256, FSMEM>>>(Qh, Kh, Vt, Mb, X);
        }
        split_bf16<<<(nA4 + 255) / 256, 256>>>((const float4*)gemms[g].A,
                                               (__nv_bfloat162*)Ahi, (__nv_bfloat162*)Alo, nA4);
        split_bf16<<<(nW4 + 255) / 256, 256>>>((const float4*)gemms[g].W,
                                               (__nv_bfloat162*)Whi, (__nv_bfloat162*)Wlo, nW4);
        gemm_mma<<<ggrid, 256, GSMEM>>>(Ahi, Alo, Whi, Wlo, gemms[g].b, gemms[g].C);
    }
}

// round 11
// speedup vs baseline: 5.4271x; 2.2612x over previous
#include <cuda_runtime.h>
#include <cuda_bf16.h>
#include <cuda_fp16.h>
#include <cstdint>

// Problem dims (fixed by reference)
#define B_   2
#define S_   2048
#define D_   1024
#define H_   16
#define HD_  64
#define NTOK (B_ * S_)   // 4096

#define QSCALE 0.18033688f   // 0.125 * log2(e): scores in log2 domain

// ---------------- scratch (no cudaMalloc allowed) ----------------
__device__ float g_X [(size_t)NTOK * D_];
__device__ float g_mbias[NTOK];
__device__ __half g_A16q[(size_t)NTOK * D_];
__device__ __half g_A16k[(size_t)NTOK * D_];
__device__ __half g_A16v[(size_t)NTOK * D_];
__device__ __half g_W16[(size_t)3 * D_ * D_];
__device__ __half g_Qh[(size_t)NTOK * D_];
__device__ __half g_Kh[(size_t)NTOK * D_];
__device__ __half g_Vh[(size_t)NTOK * D_];
__device__ __half g_Vt[(size_t)NTOK * D_];   // [B,H,HD,S]
__device__ __nv_bfloat16 g_Ahi[(size_t)NTOK * D_];
__device__ __nv_bfloat16 g_Alo[(size_t)NTOK * D_];
__device__ __nv_bfloat16 g_Whi[(size_t)D_ * D_];
__device__ __nv_bfloat16 g_Wlo[(size_t)D_ * D_];

// ================= helpers =================
__device__ __forceinline__ uint32_t smem_u32(const void* p) {
    uint32_t a;
    asm("{ .reg .u64 t; cvta.to.shared.u64 t, %1; cvt.u32.u64 %0, t; }"
        : "=r"(a) : "l"(p));
    return a;
}
#define SW128(o) ((o) ^ (((o) >> 3) & 0x70))

#define CP_ASYNC16(dst, src) \
    asm volatile("cp.async.cg.shared.global [%0], [%1], 16;" :: "r"(dst), "l"(src))
#define CP_COMMIT() asm volatile("cp.async.commit_group;" ::: "memory")
#define CP_WAIT(n)  asm volatile("cp.async.wait_group %0;" :: "n"(n) : "memory")

__device__ __forceinline__ void ldsm4(uint32_t* r, uint32_t addr) {
    asm volatile("ldmatrix.sync.aligned.m8n8.x4.shared.b16 {%0,%1,%2,%3}, [%4];"
                 : "=r"(r[0]), "=r"(r[1]), "=r"(r[2]), "=r"(r[3]) : "r"(addr));
}
__device__ __forceinline__ void mma_bf16(float* c, const uint32_t* a, const uint32_t* b) {
    asm volatile("mma.sync.aligned.m16n8k16.row.col.f32.bf16.bf16.f32 "
                 "{%0,%1,%2,%3}, {%4,%5,%6,%7}, {%8,%9}, {%0,%1,%2,%3};"
                 : "+f"(c[0]), "+f"(c[1]), "+f"(c[2]), "+f"(c[3])
                 : "r"(a[0]), "r"(a[1]), "r"(a[2]), "r"(a[3]),
                   "r"(b[0]), "r"(b[1]));
}
__device__ __forceinline__ void mma_f16(float* c, const uint32_t* a, const uint32_t* b) {
    asm volatile("mma.sync.aligned.m16n8k16.row.col.f32.f16.f16.f32 "
                 "{%0,%1,%2,%3}, {%4,%5,%6,%7}, {%8,%9}, {%0,%1,%2,%3};"
                 : "+f"(c[0]), "+f"(c[1]), "+f"(c[2]), "+f"(c[3])
                 : "r"(a[0]), "r"(a[1]), "r"(a[2]), "r"(a[3]),
                   "r"(b[0]), "r"(b[1]));
}
__device__ __forceinline__ uint32_t pack_f16x2(float lo, float hi) {
    uint32_t d;
    asm("cvt.rn.f16x2.f32 %0, %1, %2;" : "=r"(d) : "f"(hi), "f"(lo));
    return d;
}
__device__ __forceinline__ uint32_t ex2_f16x2(uint32_t x) {
    uint32_t d;
    asm("ex2.approx.f16x2 %0, %1;" : "=r"(d) : "r"(x));
    return d;
}
__device__ __forceinline__ float ex2f(float x) {
    float y;
    asm("ex2.approx.f32 %0, %1;" : "=f"(y) : "f"(x));
    return y;
}

// =================================================================
// split fp32 -> bf16 hi + bf16 lo (for the output projection)
// =================================================================
__global__ void split_bf16(const float4* __restrict__ in,
                           __nv_bfloat162* __restrict__ hi,
                           __nv_bfloat162* __restrict__ lo, int n4) {
    int i = blockIdx.x * blockDim.x + threadIdx.x;
    if (i >= n4) return;
    float4 v = in[i];
    __nv_bfloat16 h0 = __float2bfloat16(v.x);
    __nv_bfloat16 h1 = __float2bfloat16(v.y);
    __nv_bfloat16 h2 = __float2bfloat16(v.z);
    __nv_bfloat16 h3 = __float2bfloat16(v.w);
    __nv_bfloat16 l0 = __float2bfloat16(v.x - __bfloat162float(h0));
    __nv_bfloat16 l1 = __float2bfloat16(v.y - __bfloat162float(h1));
    __nv_bfloat16 l2 = __float2bfloat16(v.z - __bfloat162float(h2));
    __nv_bfloat16 l3 = __float2bfloat16(v.w - __bfloat162float(h3));
    __nv_bfloat162 ph0; ph0.x = h0; ph0.y = h1;
    __nv_bfloat162 ph1; ph1.x = h2; ph1.y = h3;
    __nv_bfloat162 pl0; pl0.x = l0; pl0.y = l1;
    __nv_bfloat162 pl1; pl1.x = l2; pl1.y = l3;
    hi[2 * i + 0] = ph0;
    hi[2 * i + 1] = ph1;
    lo[2 * i + 0] = pl0;
    lo[2 * i + 1] = pl1;
}

// fp32 -> fp16
__global__ void conv_f16(const float4* __restrict__ in, __half2* __restrict__ out,
                         int n4) {
    int i = blockIdx.x * blockDim.x + threadIdx.x;
    if (i >= n4) return;
    float4 v = in[i];
    out[2 * i + 0] = __floats2half2_rn(v.x, v.y);
    out[2 * i + 1] = __floats2half2_rn(v.z, v.w);
}

// Vh f16 [b*S+s][h*64+d] -> f16 [ (bh*64+d)*S + s ]  (per-head transpose)
__global__ void conv_vt16(const __half* __restrict__ V, __half* __restrict__ Vt) {
    __shared__ __half tile[32][34];
    const int s0 = blockIdx.x * 32;
    const int d0 = blockIdx.y * 32;
    const int bh = blockIdx.z;
    const int b = bh >> 4, h = bh & 15;
    const int tx = threadIdx.x, ty = threadIdx.y;
#pragma unroll
    for (int i = 0; i < 4; i++) {
        const int s = s0 + ty + i * 8;
        tile[ty + i * 8][tx] = V[(size_t)(b * S_ + s) * D_ + h * HD_ + d0 + tx];
    }
    __syncthreads();
#pragma unroll
    for (int i = 0; i < 4; i++) {
        const int d = d0 + ty + i * 8;
        Vt[(size_t)(bh * HD_ + d) * S_ + s0 + tx] = tile[tx][ty + i * 8];
    }
}

// =================================================================
// Mask build (dtype auto-detect: packed uint8 vs int32)
// =================================================================
__global__ void build_mask(const void* __restrict__ kpm_raw,
                           const void* __restrict__ am_raw,
                           float* __restrict__ mb) {
    __shared__ int s_u8;
    if (threadIdx.x == 0) s_u8 = 0;
    __syncthreads();
    const int* probe = (const int*)kpm_raw;
    for (int i = threadIdx.x; i < 1024; i += blockDim.x)
        if ((unsigned)probe[i] > 1u) s_u8 = 1;
    __syncthreads();
    const int is_u8 = s_u8;
    for (int i = threadIdx.x; i < NTOK; i += blockDim.x) {
        int k, a;
        if (is_u8) {
            k = ((const uint8_t*)kpm_raw)[i];
            a = ((const uint8_t*)am_raw)[i];
        } else {
            k = ((const int*)kpm_raw)[i];
            a = ((const int*)am_raw)[i];
        }
        mb[i] = (k | a) ? -1e30f : 0.0f;
    }
}

// =================================================================
// Fused QKV projection GEMM, fp16 single product.
// grid (24, 32): blockIdx.x -> [section 0..2][n-tile 0..7].
// C(section) = A(section) @ W(section)^T + bias, written as f16
// (section 0 pre-scaled by QSCALE for flash's log2-domain softmax).
// =================================================================
#define QTILE_B 16384            // 128 rows x 128 B (f16 64 cols)
#define QSTG_B  (2 * QTILE_B)    // A + W
#define QSMEM   (2 * QSTG_B)     // 65536
#define KSTEPS  16

__global__ __launch_bounds__(256, 2)
void gemm_qkv(const __half* __restrict__ Aq, const __half* __restrict__ Ak,
              const __half* __restrict__ Av, const __half* __restrict__ W16,
              const float* __restrict__ bq, const float* __restrict__ bk,
              const float* __restrict__ bv,
              __half* __restrict__ Qh, __half* __restrict__ Kh,
              __half* __restrict__ Vh) {
    extern __shared__ char smem[];
    const uint32_t sb = smem_u32(smem);
    const int tid  = threadIdx.x;
    const int wid  = tid >> 5;
    const int lane = tid & 31;
    const int wm = wid & 1;
    const int wn = wid >> 1;

    const int sec = blockIdx.x >> 3;
    const int bxn = blockIdx.x & 7;
    const __half* A = (sec == 0) ? Aq : (sec == 1) ? Ak : Av;
    const __half* W = W16 + (size_t)sec * D_ * D_ + (size_t)bxn * 128 * D_;
    const float* bias = ((sec == 0) ? bq : (sec == 1) ? bk : bv) + bxn * 128;
    __half* C = (sec == 0) ? Qh : (sec == 1) ? Kh : Vh;
    const float csc = (sec == 0) ? QSCALE : 1.0f;

    A += (size_t)blockIdx.y * 128 * D_;

    const int crow = tid >> 3;
    const int c16  = tid & 7;

    auto load_stage = [&](int ks, int stage) {
        const uint32_t stb = sb + stage * QSTG_B;
        const __half* gA = A + (size_t)ks * 64 + c16 * 8;
        const __half* gW = W + (size_t)ks * 64 + c16 * 8;
#pragma unroll
        for (int p = 0; p < 4; p++) {
            const int row = crow + p * 32;
            const uint32_t so = SW128((uint32_t)(row * 128 + c16 * 16));
            CP_ASYNC16(stb + so, gA + (size_t)row * D_);
            CP_ASYNC16(stb + QTILE_B + so, gW + (size_t)row * D_);
        }
    };

    float acc[4][4][4] = {};
    load_stage(0, 0);
    CP_COMMIT();

    for (int ks = 0; ks < KSTEPS; ks++) {
        const int stage = ks & 1;
        if (ks + 1 < KSTEPS) {
            load_stage(ks + 1, stage ^ 1);
            CP_COMMIT();
            CP_WAIT(1);
        } else {
            CP_WAIT(0);
        }
        __syncthreads();

        const uint32_t sA = sb + stage * QSTG_B;
        const uint32_t sW = sA + QTILE_B;

#pragma unroll
        for (int kk = 0; kk < 4; kk++) {
            const uint32_t bcol = kk * 32 + ((lane >> 4) << 4);
            uint32_t bh[4][2];
#pragma unroll
            for (int nb = 0; nb < 2; nb++) {
                const int row = wn * 32 + nb * 16 + (lane & 15);
                uint32_t r4[4];
                ldsm4(r4, sW + SW128((uint32_t)(row * 128) + bcol));
                bh[2 * nb][0] = r4[0]; bh[2 * nb][1] = r4[2];
                bh[2 * nb + 1][0] = r4[1]; bh[2 * nb + 1][1] = r4[3];
            }
#pragma unroll
            for (int mf = 0; mf < 4; mf++) {
                const int row = wm * 64 + mf * 16 + (lane & 15);
                uint32_t ah[4];
                ldsm4(ah, sA + SW128((uint32_t)(row * 128) + bcol));
#pragma unroll
                for (int nf = 0; nf < 4; nf++)
                    mma_f16(acc[mf][nf], ah, bh[nf]);
            }
        }
        __syncthreads();
    }

    const int r  = lane >> 2;
    const int c2 = (lane & 3) * 2;
#pragma unroll
    for (int nf = 0; nf < 4; nf++) {
        const int lcol = bxn * 128 + wn * 32 + nf * 8 + c2;
        const float b0 = __ldg(bias + wn * 32 + nf * 8 + c2);
        const float b1 = __ldg(bias + wn * 32 + nf * 8 + c2 + 1);
#pragma unroll
        for (int mf = 0; mf < 4; mf++) {
            const int grow = blockIdx.y * 128 + wm * 64 + mf * 16 + r;
            __half2 v0 = __floats2half2_rn((acc[mf][nf][0] + b0) * csc,
                                           (acc[mf][nf][1] + b1) * csc);
            __half2 v1 = __floats2half2_rn((acc[mf][nf][2] + b0) * csc,
                                           (acc[mf][nf][3] + b1) * csc);
            *(__half2*)(C + (size_t)grow * D_ + lcol) = v0;
            *(__half2*)(C + (size_t)(grow + 8) * D_ + lcol) = v1;
        }
    }
}

// =================================================================
// bf16x3 split GEMM for the output projection (unchanged, accurate)
// =================================================================
#define TILE_B  16384
#define STG_B   (4 * TILE_B)
#define GSMEM   (2 * STG_B)

__global__ __launch_bounds__(256, 1)
void gemm_mma(const __nv_bfloat16* __restrict__ Ahi, const __nv_bfloat16* __restrict__ Alo,
              const __nv_bfloat16* __restrict__ Whi, const __nv_bfloat16* __restrict__ Wlo,
              const float* __restrict__ bias, float* __restrict__ C) {
    extern __shared__ char smem[];
    const uint32_t sb = smem_u32(smem);
    const int tid  = threadIdx.x;
    const int wid  = tid >> 5;
    const int lane = tid & 31;
    const int wm = wid & 1;
    const int wn = wid >> 1;

    const size_t aoff = (size_t)blockIdx.y * 128 * D_;
    const size_t woff = (size_t)blockIdx.x * 128 * D_;
    const __nv_bfloat16* srcs[4] = {Ahi + aoff, Alo + aoff, Whi + woff, Wlo + woff};

    const int crow = tid >> 3;
    const int c16  = tid & 7;

    auto load_stage = [&](int ks, int stage) {
        const uint32_t stb = sb + stage * STG_B;
#pragma unroll
        for (int m = 0; m < 4; m++) {
            const __nv_bfloat16* g0 = srcs[m] + (size_t)ks * 64 + c16 * 8;
#pragma unroll
            for (int p = 0; p < 4; p++) {
                const int row = crow + p * 32;
                const uint32_t so = SW128((uint32_t)(row * 128 + c16 * 16));
                CP_ASYNC16(stb + m * TILE_B + so, g0 + (size_t)row * D_);
            }
        }
    };

    float acc[4][4][4] = {};
    load_stage(0, 0);
    CP_COMMIT();

    for (int ks = 0; ks < KSTEPS; ks++) {
        const int stage = ks & 1;
        if (ks + 1 < KSTEPS) {
            load_stage(ks + 1, stage ^ 1);
            CP_COMMIT();
            CP_WAIT(1);
        } else {
            CP_WAIT(0);
        }
        __syncthreads();

        const uint32_t sAh = sb + stage * STG_B;
        const uint32_t sAl = sAh + TILE_B;
        const uint32_t sWh = sAh + 2 * TILE_B;
        const uint32_t sWl = sAh + 3 * TILE_B;

#pragma unroll
        for (int kk = 0; kk < 4; kk++) {
            const uint32_t bcol = kk * 32 + ((lane >> 4) << 4);
            uint32_t bh[4][2], bl[4][2];
#pragma unroll
            for (int nb = 0; nb < 2; nb++) {
                const int row = wn * 32 + nb * 16 + (lane & 15);
                const uint32_t so = SW128((uint32_t)(row * 128) + bcol);
                uint32_t r4[4];
                ldsm4(r4, sWh + so);
                bh[2 * nb][0] = r4[0]; bh[2 * nb][1] = r4[2];
                bh[2 * nb + 1][0] = r4[1]; bh[2 * nb + 1][1] = r4[3];
                ldsm4(r4, sWl + so);
                bl[2 * nb][0] = r4[0]; bl[2 * nb][1] = r4[2];
                bl[2 * nb + 1][0] = r4[1]; bl[2 * nb + 1][1] = r4[3];
            }
#pragma unroll
            for (int mf = 0; mf < 4; mf++) {
                const int row = wm * 64 + mf * 16 + (lane & 15);
                const uint32_t so = SW128((uint32_t)(row * 128) + bcol);
                uint32_t ah[4], al[4];
                ldsm4(ah, sAh + so);
                ldsm4(al, sAl + so);
#pragma unroll
                for (int nf = 0; nf < 4; nf++) {
                    mma_bf16(acc[mf][nf], ah, bh[nf]);
                    mma_bf16(acc[mf][nf], ah, bl[nf]);
                    mma_bf16(acc[mf][nf], al, bh[nf]);
                }
            }
        }
        __syncthreads();
    }

    const int r  = lane >> 2;
    const int c2 = (lane & 3) * 2;
#pragma unroll
    for (int nf = 0; nf < 4; nf++) {
        const int gcol = blockIdx.x * 128 + wn * 32 + nf * 8 + c2;
        const float b0 = __ldg(bias + gcol);
        const float b1 = __ldg(bias + gcol + 1);
#pragma unroll
        for (int mf = 0; mf < 4; mf++) {
            const int grow = blockIdx.y * 128 + wm * 64 + mf * 16 + r;
            float2 v0 = {acc[mf][nf][0] + b0, acc[mf][nf][1] + b1};
            float2 v1 = {acc[mf][nf][2] + b0, acc[mf][nf][3] + b1};
            *(float2*)(C + (size_t)grow * D_ + gcol) = v0;
            *(float2*)(C + (size_t)(grow + 8) * D_ + gcol) = v1;
        }
    }
}

// =================================================================
// Flash attention, fp16 mma, log2-domain softmax with ex2.f16x2,
// row-sum l via ones-MMA (no shuffles for l).
// =================================================================
#define FSQ   0
#define FSK   16384
#define FSV   (16384 + 16384)
#define FSMB  (FSV + 16384)
#define FSMEM (FSMB + 512)
#define NKT   (S_ / 64)

__global__ __launch_bounds__(256, 1)
void flash_mma(const __half* __restrict__ Qh, const __half* __restrict__ Kh,
               const __half* __restrict__ Vt, const float* __restrict__ mbias,
               float* __restrict__ O) {
    extern __shared__ char smem[];
    const uint32_t sb = smem_u32(smem);
    const int tid  = threadIdx.x;
    const int wid  = tid >> 5;
    const int lane = tid & 31;
    const int q0 = blockIdx.x * 128;
    const int h  = blockIdx.y;
    const int b  = blockIdx.z;

    const int crow = tid >> 3;
    const int c16  = tid & 7;

    const __half* Qg = Qh + (size_t)(b * S_ + q0) * D_ + h * HD_;
    const __half* Kg = Kh + (size_t)b * S_ * D_ + h * HD_;
    const __half* Vg = Vt + (size_t)(b * H_ + h) * HD_ * S_;
    const float*  Mg = mbias + b * S_;

#pragma unroll
    for (int p = 0; p < 4; p++) {
        const int row = crow + p * 32;
        CP_ASYNC16(sb + FSQ + SW128((uint32_t)(row * 128 + c16 * 16)),
                   Qg + (size_t)row * D_ + c16 * 8);
    }
    auto load_stage = [&](int kt, int st) {
#pragma unroll
        for (int p = 0; p < 2; p++) {
            const int row = crow + p * 32;
            const uint32_t so = SW128((uint32_t)(row * 128 + c16 * 16));
            CP_ASYNC16(sb + FSK + st * 8192 + so,
                       Kg + (size_t)(kt * 64 + row) * D_ + c16 * 8);
            CP_ASYNC16(sb + FSV + st * 8192 + so,
                       Vg + (size_t)row * S_ + kt * 64 + c16 * 8);
        }
        if (tid < 16)
            CP_ASYNC16(sb + FSMB + st * 256 + tid * 16, Mg + kt * 64 + tid * 4);
    };
    load_stage(0, 0);
    CP_COMMIT();

    uint32_t qf[4][4];
    float o[8][4] = {};
    float lfrag[4] = {};
    float m0 = -1e30f, m1 = -1e30f;
    const uint32_t ones2[2] = {0x3C003C00u, 0x3C003C00u};   // f16 1.0 x2

    const int lrow = lane & 15;
    const uint32_t lcol = (uint32_t)((lane >> 4) << 4);

    for (int kt = 0; kt < NKT; kt++) {
        const int st = kt & 1;
        if (kt + 1 < NKT) {
            load_stage(kt + 1, st ^ 1);
            CP_COMMIT();
            CP_WAIT(1);
        } else {
            CP_WAIT(0);
        }
        __syncthreads();

        if (kt == 0) {
#pragma unroll
            for (int ks = 0; ks < 4; ks++)
                ldsm4(qf[ks], sb + FSQ +
                      SW128((uint32_t)((wid * 16 + lrow) * 128 + ks * 32) + lcol));
        }

        const uint32_t sbK = sb + FSK + st * 8192;
        const uint32_t sbV = sb + FSV + st * 8192;
        const float* mbp = (const float*)(smem + FSMB + st * 256);

        // ---- S = Q K^T (log2 domain: Q pre-scaled by 0.125*log2e) ----
        float s[8][4] = {};
#pragma unroll
        for (int ks = 0; ks < 4; ks++) {
#pragma unroll
            for (int nb = 0; nb < 4; nb++) {
                uint32_t r4[4];
                ldsm4(r4, sbK + SW128((uint32_t)((nb * 16 + lrow) * 128 + ks * 32) + lcol));
                uint32_t b0[2] = {r4[0], r4[2]};
                uint32_t b1[2] = {r4[1], r4[3]};
                mma_f16(s[2 * nb], qf[ks], b0);
                mma_f16(s[2 * nb + 1], qf[ks], b1);
            }
        }

        // ---- mask + running max ----
        const int cbase = (lane & 3) * 2;
        float tm0 = -3e38f, tm1 = -3e38f;
#pragma unroll
        for (int nf = 0; nf < 8; nf++) {
            float2 mv = *(const float2*)(mbp + nf * 8 + cbase);
            s[nf][0] += mv.x; s[nf][1] += mv.y;
            s[nf][2] += mv.x; s[nf][3] += mv.y;
            tm0 = fmaxf(tm0, fmaxf(s[nf][0], s[nf][1]));
            tm1 = fmaxf(tm1, fmaxf(s[nf][2], s[nf][3]));
        }
        tm0 = fmaxf(tm0, __shfl_xor_sync(0xffffffffu, tm0, 1));
        tm0 = fmaxf(tm0, __shfl_xor_sync(0xffffffffu, tm0, 2));
        tm1 = fmaxf(tm1, __shfl_xor_sync(0xffffffffu, tm1, 1));
        tm1 = fmaxf(tm1, __shfl_xor_sync(0xffffffffu, tm1, 2));

        const float mn0 = fmaxf(m0, tm0);
        const float mn1 = fmaxf(m1, tm1);
        const float cr0 = ex2f(m0 - mn0);
        const float cr1 = ex2f(m1 - mn1);
        m0 = mn0; m1 = mn1;

        // ---- P = 2^(S-m) directly as f16x2 fragments ----
        uint32_t pa[4][4];
#pragma unroll
        for (int nf = 0; nf < 8; nf++) {
            uint32_t x01 = pack_f16x2(s[nf][0] - m0, s[nf][1] - m0);
            uint32_t x23 = pack_f16x2(s[nf][2] - m1, s[nf][3] - m1);
            const int kk = nf >> 1;
            if ((nf & 1) == 0) {
                pa[kk][0] = ex2_f16x2(x01);
                pa[kk][1] = ex2_f16x2(x23);
            } else {
                pa[kk][2] = ex2_f16x2(x01);
                pa[kk][3] = ex2_f16x2(x23);
            }
        }

        // ---- rescale running O and l ----
#pragma unroll
        for (int nf = 0; nf < 8; nf++) {
            o[nf][0] *= cr0; o[nf][1] *= cr0;
            o[nf][2] *= cr1; o[nf][3] *= cr1;
        }
        lfrag[0] *= cr0; lfrag[1] *= cr0;
        lfrag[2] *= cr1; lfrag[3] *= cr1;

        // ---- l += P * ones (row sums; every thread gets its rows' sums) ----
#pragma unroll
        for (int kk = 0; kk < 4; kk++)
            mma_f16(lfrag, pa[kk], ones2);

        // ---- O += P V ----
#pragma unroll
        for (int kk = 0; kk < 4; kk++) {
#pragma unroll
            for (int nb = 0; nb < 4; nb++) {
                uint32_t r4[4];
                ldsm4(r4, sbV + SW128((uint32_t)((nb * 16 + lrow) * 128 + kk * 32) + lcol));
                uint32_t b0[2] = {r4[0], r4[2]};
                uint32_t b1[2] = {r4[1], r4[3]};
                mma_f16(o[2 * nb], pa[kk], b0);
                mma_f16(o[2 * nb + 1], pa[kk], b1);
            }
        }
        __syncthreads();
    }

    // ---- write O ----
    const float inv0 = 1.0f / lfrag[0];
    const float inv1 = 1.0f / lfrag[2];
    const int r = lane >> 2;
    const int tok0 = b * S_ + q0 + wid * 16 + r;
#pragma unroll
    for (int nf = 0; nf < 8; nf++) {
        const int col = h * HD_ + nf * 8 + (lane & 3) * 2;
        float2 v0 = {o[nf][0] * inv0, o[nf][1] * inv0};
        float2 v1 = {o[nf][2] * inv1, o[nf][3] * inv1};
        *(float2*)(O + (size_t)tok0 * D_ + col) = v0;
        *(float2*)(O + (size_t)(tok0 + 8) * D_ + col) = v1;
    }
}

// =================================================================
// launch
// =================================================================
extern "C" void kernel_launch(void* const* d_in, const int* in_sizes, int n_in,
                              void* d_out, int out_size) {
    const float* query = (const float*)d_in[0];
    const float* key   = (const float*)d_in[1];
    const float* value = (const float*)d_in[2];
    const void*  kpm   = d_in[3];
    const void*  am    = d_in[4];
    // d_in[5] = is_casual (ignored in eval mode)
    const float* Wq = (const float*)d_in[6];
    const float* bq = (const float*)d_in[7];
    const float* Wk = (const float*)d_in[8];
    const float* bk = (const float*)d_in[9];
    const float* Wv = (const float*)d_in[10];
    const float* bv = (const float*)d_in[11];
    const float* Wo = (const float*)d_in[12];
    const float* bo = (const float*)d_in[13];
    float* out = (float*)d_out;

    float *X, *Mb;
    __half *A16q, *A16k, *A16v, *W16, *Qh, *Kh, *Vh, *Vt;
    __nv_bfloat16 *Ahi, *Alo, *Whi, *Wlo;
    cudaGetSymbolAddress((void**)&X,  g_X);
    cudaGetSymbolAddress((void**)&Mb, g_mbias);
    cudaGetSymbolAddress((void**)&A16q, g_A16q);
    cudaGetSymbolAddress((void**)&A16k, g_A16k);
    cudaGetSymbolAddress((void**)&A16v, g_A16v);
    cudaGetSymbolAddress((void**)&W16, g_W16);
    cudaGetSymbolAddress((void**)&Qh, g_Qh);
    cudaGetSymbolAddress((void**)&Kh, g_Kh);
    cudaGetSymbolAddress((void**)&Vh, g_Vh);
    cudaGetSymbolAddress((void**)&Vt, g_Vt);
    cudaGetSymbolAddress((void**)&Ahi, g_Ahi);
    cudaGetSymbolAddress((void**)&Alo, g_Alo);
    cudaGetSymbolAddress((void**)&Whi, g_Whi);
    cudaGetSymbolAddress((void**)&Wlo, g_Wlo);

    build_mask<<<1, 1024>>>(kpm, am, Mb);

    cudaFuncSetAttribute(gemm_qkv, cudaFuncAttributeMaxDynamicSharedMemorySize, QSMEM);
    cudaFuncSetAttribute(gemm_mma, cudaFuncAttributeMaxDynamicSharedMemorySize, GSMEM);
    cudaFuncSetAttribute(flash_mma, cudaFuncAttributeMaxDynamicSharedMemorySize, FSMEM);

    const int nA4 = NTOK * D_ / 4;
    const int nW4 = D_ * D_ / 4;

    // fp32 -> f16 inputs (activations + QKV weights)
    conv_f16<<<(nA4 + 255) / 256, 256>>>((const float4*)query, (__half2*)A16q, nA4);
    conv_f16<<<(nA4 + 255) / 256, 256>>>((const float4*)key,   (__half2*)A16k, nA4);
    conv_f16<<<(nA4 + 255) / 256, 256>>>((const float4*)value, (__half2*)A16v, nA4);
    conv_f16<<<(nW4 + 255) / 256, 256>>>((const float4*)Wq, (__half2*)(W16 + 0 * (size_t)D_ * D_), nW4);
    conv_f16<<<(nW4 + 255) / 256, 256>>>((const float4*)Wk, (__half2*)(W16 + 1 * (size_t)D_ * D_), nW4);
    conv_f16<<<(nW4 + 255) / 256, 256>>>((const float4*)Wv, (__half2*)(W16 + 2 * (size_t)D_ * D_), nW4);

    // fused QKV projections -> Qh (scaled), Kh, Vh
    gemm_qkv<<<dim3(24, NTOK / 128), 256, QSMEM>>>(A16q, A16k, A16v, W16,
                                                   bq, bk, bv, Qh, Kh, Vh);

    // V transpose per head, then flash -> X (fp32)
    conv_vt16<<<dim3(S_ / 32, HD_ / 32, B_ * H_), dim3(32, 8)>>>(Vh, Vt);
    flash_mma<<<dim3(S_ / 128, H_, B_), 256, FSMEM>>>(Qh, Kh, Vt, Mb, X);

    // output projection: accurate bf16x3 path
    split_bf16<<<(nA4 + 255) / 256, 256>>>((const float4*)X,
                                           (__nv_bfloat162*)Ahi, (__nv_bfloat162*)Alo, nA4);
    split_bf16<<<(nW4 + 255) / 256, 256>>>((const float4*)Wo,
                                           (__nv_bfloat162*)Whi, (__nv_bfloat162*)Wlo, nW4);
    gemm_mma<<<dim3(D_ / 128, NTOK / 128), 256, GSMEM>>>(Ahi, Alo, Whi, Wlo, bo, out);
}

// round 13
// speedup vs baseline: 6.6602x; 1.2272x over previous
#include <cuda_runtime.h>
#include <cuda_fp16.h>
#include <cstdint>

// Problem dims (fixed by reference)
#define B_   2
#define S_   2048
#define D_   1024
#define H_   16
#define HD_  64
#define NTOK (B_ * S_)   // 4096

#define QSCALE 0.18033688f   // 0.125 * log2(e): scores in log2 domain

// ---------------- scratch (no cudaMalloc allowed) ----------------
__device__ float g_mbias[NTOK];
__device__ __half g_A16q[(size_t)NTOK * D_];
__device__ __half g_A16k[(size_t)NTOK * D_];
__device__ __half g_A16v[(size_t)NTOK * D_];
__device__ __half g_W16[(size_t)3 * D_ * D_];   // Wq, Wk, Wv
__device__ __half g_W16o[(size_t)D_ * D_];      // Wo
__device__ __half g_Qh[(size_t)NTOK * D_];
__device__ __half g_Kh[(size_t)NTOK * D_];
__device__ __half g_Vh[(size_t)NTOK * D_];
__device__ __half g_Vt[(size_t)NTOK * D_];      // [B,H,HD,S]
__device__ __half g_Xh[(size_t)NTOK * D_];      // attention output (f16)

// ================= helpers =================
__device__ __forceinline__ uint32_t smem_u32(const void* p) {
    uint32_t a;
    asm("{ .reg .u64 t; cvta.to.shared.u64 t, %1; cvt.u32.u64 %0, t; }"
        : "=r"(a) : "l"(p));
    return a;
}
#define SW128(o) ((o) ^ (((o) >> 3) & 0x70))

#define CP_ASYNC16(dst, src) \
    asm volatile("cp.async.cg.shared.global [%0], [%1], 16;" :: "r"(dst), "l"(src))
#define CP_COMMIT() asm volatile("cp.async.commit_group;" ::: "memory")
#define CP_WAIT(n)  asm volatile("cp.async.wait_group %0;" :: "n"(n) : "memory")

__device__ __forceinline__ void ldsm4(uint32_t* r, uint32_t addr) {
    asm volatile("ldmatrix.sync.aligned.m8n8.x4.shared.b16 {%0,%1,%2,%3}, [%4];"
                 : "=r"(r[0]), "=r"(r[1]), "=r"(r[2]), "=r"(r[3]) : "r"(addr));
}
__device__ __forceinline__ void mma_f16(float* c, const uint32_t* a, const uint32_t* b) {
    asm volatile("mma.sync.aligned.m16n8k16.row.col.f32.f16.f16.f32 "
                 "{%0,%1,%2,%3}, {%4,%5,%6,%7}, {%8,%9}, {%0,%1,%2,%3};"
                 : "+f"(c[0]), "+f"(c[1]), "+f"(c[2]), "+f"(c[3])
                 : "r"(a[0]), "r"(a[1]), "r"(a[2]), "r"(a[3]),
                   "r"(b[0]), "r"(b[1]));
}
__device__ __forceinline__ uint32_t pack_f16x2(float lo, float hi) {
    uint32_t d;
    asm("cvt.rn.f16x2.f32 %0, %1, %2;" : "=r"(d) : "f"(hi), "f"(lo));
    return d;
}
__device__ __forceinline__ uint32_t ex2_f16x2(uint32_t x) {
    uint32_t d;
    asm("ex2.approx.f16x2 %0, %1;" : "=r"(d) : "r"(x));
    return d;
}
__device__ __forceinline__ float ex2f(float x) {
    float y;
    asm("ex2.approx.f32 %0, %1;" : "=f"(y) : "f"(x));
    return y;
}

// =================================================================
// Fused fp32 -> fp16 conversion over 7 source arrays (one launch)
// =================================================================
struct ConvArgs {
    const float4* in[7];
    __half2*      out[7];
    int           n4[7];
};

__global__ void conv_all(ConvArgs args) {
    int i = blockIdx.x * blockDim.x + threadIdx.x;
#pragma unroll
    for (int s = 0; s < 7; s++) {
        if (i < args.n4[s]) {
            float4 v = args.in[s][i];
            args.out[s][2 * i + 0] = __floats2half2_rn(v.x, v.y);
            args.out[s][2 * i + 1] = __floats2half2_rn(v.z, v.w);
            return;
        }
        i -= args.n4[s];
    }
}

// Vh f16 [b*S+s][h*64+d] -> f16 [ (bh*64+d)*S + s ]  (per-head transpose)
__global__ void conv_vt16(const __half* __restrict__ V, __half* __restrict__ Vt) {
    __shared__ __half tile[32][34];
    const int s0 = blockIdx.x * 32;
    const int d0 = blockIdx.y * 32;
    const int bh = blockIdx.z;
    const int b = bh >> 4, h = bh & 15;
    const int tx = threadIdx.x, ty = threadIdx.y;
#pragma unroll
    for (int i = 0; i < 4; i++) {
        const int s = s0 + ty + i * 8;
        tile[ty + i * 8][tx] = V[(size_t)(b * S_ + s) * D_ + h * HD_ + d0 + tx];
    }
    __syncthreads();
#pragma unroll
    for (int i = 0; i < 4; i++) {
        const int d = d0 + ty + i * 8;
        Vt[(size_t)(bh * HD_ + d) * S_ + s0 + tx] = tile[tx][ty + i * 8];
    }
}

// =================================================================
// Mask build (dtype auto-detect: packed uint8 vs int32)
// =================================================================
__global__ void build_mask(const void* __restrict__ kpm_raw,
                           const void* __restrict__ am_raw,
                           float* __restrict__ mb) {
    __shared__ int s_u8;
    if (threadIdx.x == 0) s_u8 = 0;
    __syncthreads();
    const int* probe = (const int*)kpm_raw;
    for (int i = threadIdx.x; i < 1024; i += blockDim.x)
        if ((unsigned)probe[i] > 1u) s_u8 = 1;
    __syncthreads();
    const int is_u8 = s_u8;
    for (int i = threadIdx.x; i < NTOK; i += blockDim.x) {
        int k, a;
        if (is_u8) {
            k = ((const uint8_t*)kpm_raw)[i];
            a = ((const uint8_t*)am_raw)[i];
        } else {
            k = ((const int*)kpm_raw)[i];
            a = ((const int*)am_raw)[i];
        }
        mb[i] = (k | a) ? -1e30f : 0.0f;
    }
}

// =================================================================
// Fused QKV projection GEMM, fp16 single product.
// grid (24, 32): blockIdx.x -> [section 0..2][n-tile 0..7].
// =================================================================
#define QTILE_B 16384            // 128 rows x 128 B (f16 64 cols)
#define QSTG_B  (2 * QTILE_B)    // A + W
#define QSMEM   (2 * QSTG_B)     // 65536
#define KSTEPS  16

__global__ __launch_bounds__(256, 2)
void gemm_qkv(const __half* __restrict__ Aq, const __half* __restrict__ Ak,
              const __half* __restrict__ Av, const __half* __restrict__ W16,
              const float* __restrict__ bq, const float* __restrict__ bk,
              const float* __restrict__ bv,
              __half* __restrict__ Qh, __half* __restrict__ Kh,
              __half* __restrict__ Vh) {
    extern __shared__ char smem[];
    const uint32_t sb = smem_u32(smem);
    const int tid  = threadIdx.x;
    const int wid  = tid >> 5;
    const int lane = tid & 31;
    const int wm = wid & 1;
    const int wn = wid >> 1;

    const int sec = blockIdx.x >> 3;
    const int bxn = blockIdx.x & 7;
    const __half* A = (sec == 0) ? Aq : (sec == 1) ? Ak : Av;
    const __half* W = W16 + (size_t)sec * D_ * D_ + (size_t)bxn * 128 * D_;
    const float* bias = ((sec == 0) ? bq : (sec == 1) ? bk : bv) + bxn * 128;
    __half* C = (sec == 0) ? Qh : (sec == 1) ? Kh : Vh;
    const float csc = (sec == 0) ? QSCALE : 1.0f;

    A += (size_t)blockIdx.y * 128 * D_;

    const int crow = tid >> 3;
    const int c16  = tid & 7;

    auto load_stage = [&](int ks, int stage) {
        const uint32_t stb = sb + stage * QSTG_B;
        const __half* gA = A + (size_t)ks * 64 + c16 * 8;
        const __half* gW = W + (size_t)ks * 64 + c16 * 8;
#pragma unroll
        for (int p = 0; p < 4; p++) {
            const int row = crow + p * 32;
            const uint32_t so = SW128((uint32_t)(row * 128 + c16 * 16));
            CP_ASYNC16(stb + so, gA + (size_t)row * D_);
            CP_ASYNC16(stb + QTILE_B + so, gW + (size_t)row * D_);
        }
    };

    float acc[4][4][4] = {};
    load_stage(0, 0);
    CP_COMMIT();

    for (int ks = 0; ks < KSTEPS; ks++) {
        const int stage = ks & 1;
        if (ks + 1 < KSTEPS) {
            load_stage(ks + 1, stage ^ 1);
            CP_COMMIT();
            CP_WAIT(1);
        } else {
            CP_WAIT(0);
        }
        __syncthreads();

        const uint32_t sA = sb + stage * QSTG_B;
        const uint32_t sW = sA + QTILE_B;

#pragma unroll
        for (int kk = 0; kk < 4; kk++) {
            const uint32_t bcol = kk * 32 + ((lane >> 4) << 4);
            uint32_t bh[4][2];
#pragma unroll
            for (int nb = 0; nb < 2; nb++) {
                const int row = wn * 32 + nb * 16 + (lane & 15);
                uint32_t r4[4];
                ldsm4(r4, sW + SW128((uint32_t)(row * 128) + bcol));
                bh[2 * nb][0] = r4[0]; bh[2 * nb][1] = r4[2];
                bh[2 * nb + 1][0] = r4[1]; bh[2 * nb + 1][1] = r4[3];
            }
#pragma unroll
            for (int mf = 0; mf < 4; mf++) {
                const int row = wm * 64 + mf * 16 + (lane & 15);
                uint32_t ah[4];
                ldsm4(ah, sA + SW128((uint32_t)(row * 128) + bcol));
#pragma unroll
                for (int nf = 0; nf < 4; nf++)
                    mma_f16(acc[mf][nf], ah, bh[nf]);
            }
        }
        __syncthreads();
    }

    const int r  = lane >> 2;
    const int c2 = (lane & 3) * 2;
#pragma unroll
    for (int nf = 0; nf < 4; nf++) {
        const int lcol = bxn * 128 + wn * 32 + nf * 8 + c2;
        const float b0 = __ldg(bias + wn * 32 + nf * 8 + c2);
        const float b1 = __ldg(bias + wn * 32 + nf * 8 + c2 + 1);
#pragma unroll
        for (int mf = 0; mf < 4; mf++) {
            const int grow = blockIdx.y * 128 + wm * 64 + mf * 16 + r;
            __half2 v0 = __floats2half2_rn((acc[mf][nf][0] + b0) * csc,
                                           (acc[mf][nf][1] + b1) * csc);
            __half2 v1 = __floats2half2_rn((acc[mf][nf][2] + b0) * csc,
                                           (acc[mf][nf][3] + b1) * csc);
            *(__half2*)(C + (size_t)grow * D_ + lcol) = v0;
            *(__half2*)(C + (size_t)(grow + 8) * D_ + lcol) = v1;
        }
    }
}

// =================================================================
// Output projection GEMM, fp16 single product, fp32 output.
// grid (8, 32). out = Xh @ Wo^T + bo
// =================================================================
__global__ __launch_bounds__(256, 2)
void gemm_out(const __half* __restrict__ Xh, const __half* __restrict__ Wo16,
              const float* __restrict__ bias, float* __restrict__ C) {
    extern __shared__ char smem[];
    const uint32_t sb = smem_u32(smem);
    const int tid  = threadIdx.x;
    const int wid  = tid >> 5;
    const int lane = tid & 31;
    const int wm = wid & 1;
    const int wn = wid >> 1;

    const __half* A = Xh + (size_t)blockIdx.y * 128 * D_;
    const __half* W = Wo16 + (size_t)blockIdx.x * 128 * D_;

    const int crow = tid >> 3;
    const int c16  = tid & 7;

    auto load_stage = [&](int ks, int stage) {
        const uint32_t stb = sb + stage * QSTG_B;
        const __half* gA = A + (size_t)ks * 64 + c16 * 8;
        const __half* gW = W + (size_t)ks * 64 + c16 * 8;
#pragma unroll
        for (int p = 0; p < 4; p++) {
            const int row = crow + p * 32;
            const uint32_t so = SW128((uint32_t)(row * 128 + c16 * 16));
            CP_ASYNC16(stb + so, gA + (size_t)row * D_);
            CP_ASYNC16(stb + QTILE_B + so, gW + (size_t)row * D_);
        }
    };

    float acc[4][4][4] = {};
    load_stage(0, 0);
    CP_COMMIT();

    for (int ks = 0; ks < KSTEPS; ks++) {
        const int stage = ks & 1;
        if (ks + 1 < KSTEPS) {
            load_stage(ks + 1, stage ^ 1);
            CP_COMMIT();
            CP_WAIT(1);
        } else {
            CP_WAIT(0);
        }
        __syncthreads();

        const uint32_t sA = sb + stage * QSTG_B;
        const uint32_t sW = sA + QTILE_B;

#pragma unroll
        for (int kk = 0; kk < 4; kk++) {
            const uint32_t bcol = kk * 32 + ((lane >> 4) << 4);
            uint32_t bh[4][2];
#pragma unroll
            for (int nb = 0; nb < 2; nb++) {
                const int row = wn * 32 + nb * 16 + (lane & 15);
                uint32_t r4[4];
                ldsm4(r4, sW + SW128((uint32_t)(row * 128) + bcol));
                bh[2 * nb][0] = r4[0]; bh[2 * nb][1] = r4[2];
                bh[2 * nb + 1][0] = r4[1]; bh[2 * nb + 1][1] = r4[3];
            }
#pragma unroll
            for (int mf = 0; mf < 4; mf++) {
                const int row = wm * 64 + mf * 16 + (lane & 15);
                uint32_t ah[4];
                ldsm4(ah, sA + SW128((uint32_t)(row * 128) + bcol));
#pragma unroll
                for (int nf = 0; nf < 4; nf++)
                    mma_f16(acc[mf][nf], ah, bh[nf]);
            }
        }
        __syncthreads();
    }

    const int r  = lane >> 2;
    const int c2 = (lane & 3) * 2;
#pragma unroll
    for (int nf = 0; nf < 4; nf++) {
        const int gcol = blockIdx.x * 128 + wn * 32 + nf * 8 + c2;
        const float b0 = __ldg(bias + gcol);
        const float b1 = __ldg(bias + gcol + 1);
#pragma unroll
        for (int mf = 0; mf < 4; mf++) {
            const int grow = blockIdx.y * 128 + wm * 64 + mf * 16 + r;
            float2 v0 = {acc[mf][nf][0] + b0, acc[mf][nf][1] + b1};
            float2 v1 = {acc[mf][nf][2] + b0, acc[mf][nf][3] + b1};
            *(float2*)(C + (size_t)grow * D_ + gcol) = v0;
            *(float2*)(C + (size_t)(grow + 8) * D_ + gcol) = v1;
        }
    }
}

// =================================================================
// Flash attention, fp16 mma, log2-domain softmax, ones-MMA row sums.
// Writes X as f16.
// =================================================================
#define FSQ   0
#define FSK   16384
#define FSV   (16384 + 16384)
#define FSMB  (FSV + 16384)
#define FSMEM (FSMB + 512)
#define NKT   (S_ / 64)

__global__ __launch_bounds__(256, 1)
void flash_mma(const __half* __restrict__ Qh, const __half* __restrict__ Kh,
               const __half* __restrict__ Vt, const float* __restrict__ mbias,
               __half* __restrict__ O) {
    extern __shared__ char smem[];
    const uint32_t sb = smem_u32(smem);
    const int tid  = threadIdx.x;
    const int wid  = tid >> 5;
    const int lane = tid & 31;
    const int q0 = blockIdx.x * 128;
    const int h  = blockIdx.y;
    const int b  = blockIdx.z;

    const int crow = tid >> 3;
    const int c16  = tid & 7;

    const __half* Qg = Qh + (size_t)(b * S_ + q0) * D_ + h * HD_;
    const __half* Kg = Kh + (size_t)b * S_ * D_ + h * HD_;
    const __half* Vg = Vt + (size_t)(b * H_ + h) * HD_ * S_;
    const float*  Mg = mbias + b * S_;

#pragma unroll
    for (int p = 0; p < 4; p++) {
        const int row = crow + p * 32;
        CP_ASYNC16(sb + FSQ + SW128((uint32_t)(row * 128 + c16 * 16)),
                   Qg + (size_t)row * D_ + c16 * 8);
    }
    auto load_stage = [&](int kt, int st) {
#pragma unroll
        for (int p = 0; p < 2; p++) {
            const int row = crow + p * 32;
            const uint32_t so = SW128((uint32_t)(row * 128 + c16 * 16));
            CP_ASYNC16(sb + FSK + st * 8192 + so,
                       Kg + (size_t)(kt * 64 + row) * D_ + c16 * 8);
            CP_ASYNC16(sb + FSV + st * 8192 + so,
                       Vg + (size_t)row * S_ + kt * 64 + c16 * 8);
        }
        if (tid < 16)
            CP_ASYNC16(sb + FSMB + st * 256 + tid * 16, Mg + kt * 64 + tid * 4);
    };
    load_stage(0, 0);
    CP_COMMIT();

    uint32_t qf[4][4];
    float o[8][4] = {};
    float lfrag[4] = {};
    float m0 = -1e30f, m1 = -1e30f;
    const uint32_t ones2[2] = {0x3C003C00u, 0x3C003C00u};   // f16 1.0 x2

    const int lrow = lane & 15;
    const uint32_t lcol = (uint32_t)((lane >> 4) << 4);

    for (int kt = 0; kt < NKT; kt++) {
        const int st = kt & 1;
        if (kt + 1 < NKT) {
            load_stage(kt + 1, st ^ 1);
            CP_COMMIT();
            CP_WAIT(1);
        } else {
            CP_WAIT(0);
        }
        __syncthreads();

        if (kt == 0) {
#pragma unroll
            for (int ks = 0; ks < 4; ks++)
                ldsm4(qf[ks], sb + FSQ +
                      SW128((uint32_t)((wid * 16 + lrow) * 128 + ks * 32) + lcol));
        }

        const uint32_t sbK = sb + FSK + st * 8192;
        const uint32_t sbV = sb + FSV + st * 8192;
        const float* mbp = (const float*)(smem + FSMB + st * 256);

        // ---- S = Q K^T (log2 domain) ----
        float s[8][4] = {};
#pragma unroll
        for (int ks = 0; ks < 4; ks++) {
#pragma unroll
            for (int nb = 0; nb < 4; nb++) {
                uint32_t r4[4];
                ldsm4(r4, sbK + SW128((uint32_t)((nb * 16 + lrow) * 128 + ks * 32) + lcol));
                uint32_t b0[2] = {r4[0], r4[2]};
                uint32_t b1[2] = {r4[1], r4[3]};
                mma_f16(s[2 * nb], qf[ks], b0);
                mma_f16(s[2 * nb + 1], qf[ks], b1);
            }
        }

        // ---- mask + running max ----
        const int cbase = (lane & 3) * 2;
        float tm0 = -3e38f, tm1 = -3e38f;
#pragma unroll
        for (int nf = 0; nf < 8; nf++) {
            float2 mv = *(const float2*)(mbp + nf * 8 + cbase);
            s[nf][0] += mv.x; s[nf][1] += mv.y;
            s[nf][2] += mv.x; s[nf][3] += mv.y;
            tm0 = fmaxf(tm0, fmaxf(s[nf][0], s[nf][1]));
            tm1 = fmaxf(tm1, fmaxf(s[nf][2], s[nf][3]));
        }
        tm0 = fmaxf(tm0, __shfl_xor_sync(0xffffffffu, tm0, 1));
        tm0 = fmaxf(tm0, __shfl_xor_sync(0xffffffffu, tm0, 2));
        tm1 = fmaxf(tm1, __shfl_xor_sync(0xffffffffu, tm1, 1));
        tm1 = fmaxf(tm1, __shfl_xor_sync(0xffffffffu, tm1, 2));

        const float mn0 = fmaxf(m0, tm0);
        const float mn1 = fmaxf(m1, tm1);
        const float cr0 = ex2f(m0 - mn0);
        const float cr1 = ex2f(m1 - mn1);
        m0 = mn0; m1 = mn1;

        // ---- P = 2^(S-m) as f16x2 fragments ----
        uint32_t pa[4][4];
#pragma unroll
        for (int nf = 0; nf < 8; nf++) {
            uint32_t x01 = pack_f16x2(s[nf][0] - m0, s[nf][1] - m0);
            uint32_t x23 = pack_f16x2(s[nf][2] - m1, s[nf][3] - m1);
            const int kk = nf >> 1;
            if ((nf & 1) == 0) {
                pa[kk][0] = ex2_f16x2(x01);
                pa[kk][1] = ex2_f16x2(x23);
            } else {
                pa[kk][2] = ex2_f16x2(x01);
                pa[kk][3] = ex2_f16x2(x23);
            }
        }

        // ---- rescale O, l ----
#pragma unroll
        for (int nf = 0; nf < 8; nf++) {
            o[nf][0] *= cr0; o[nf][1] *= cr0;
            o[nf][2] *= cr1; o[nf][3] *= cr1;
        }
        lfrag[0] *= cr0; lfrag[1] *= cr0;
        lfrag[2] *= cr1; lfrag[3] *= cr1;

        // ---- l += P * ones ----
#pragma unroll
        for (int kk = 0; kk < 4; kk++)
            mma_f16(lfrag, pa[kk], ones2);

        // ---- O += P V ----
#pragma unroll
        for (int kk = 0; kk < 4; kk++) {
#pragma unroll
            for (int nb = 0; nb < 4; nb++) {
                uint32_t r4[4];
                ldsm4(r4, sbV + SW128((uint32_t)((nb * 16 + lrow) * 128 + kk * 32) + lcol));
                uint32_t b0[2] = {r4[0], r4[2]};
                uint32_t b1[2] = {r4[1], r4[3]};
                mma_f16(o[2 * nb], pa[kk], b0);
                mma_f16(o[2 * nb + 1], pa[kk], b1);
            }
        }
        __syncthreads();
    }

    // ---- write X as f16 ----
    const float inv0 = 1.0f / lfrag[0];
    const float inv1 = 1.0f / lfrag[2];
    const int r = lane >> 2;
    const int tok0 = b * S_ + q0 + wid * 16 + r;
#pragma unroll
    for (int nf = 0; nf < 8; nf++) {
        const int col = h * HD_ + nf * 8 + (lane & 3) * 2;
        *(__half2*)(O + (size_t)tok0 * D_ + col) =
            __floats2half2_rn(o[nf][0] * inv0, o[nf][1] * inv0);
        *(__half2*)(O + (size_t)(tok0 + 8) * D_ + col) =
            __floats2half2_rn(o[nf][2] * inv1, o[nf][3] * inv1);
    }
}

// =================================================================
// launch
// =================================================================
extern "C" void kernel_launch(void* const* d_in, const int* in_sizes, int n_in,
                              void* d_out, int out_size) {
    const float* query = (const float*)d_in[0];
    const float* key   = (const float*)d_in[1];
    const float* value = (const float*)d_in[2];
    const void*  kpm   = d_in[3];
    const void*  am    = d_in[4];
    // d_in[5] = is_casual (ignored in eval mode)
    const float* Wq = (const float*)d_in[6];
    const float* bq = (const float*)d_in[7];
    const float* Wk = (const float*)d_in[8];
    const float* bk = (const float*)d_in[9];
    const float* Wv = (const float*)d_in[10];
    const float* bv = (const float*)d_in[11];
    const float* Wo = (const float*)d_in[12];
    const float* bo = (const float*)d_in[13];
    float* out = (float*)d_out;

    float* Mb;
    __half *A16q, *A16k, *A16v, *W16, *W16o, *Qh, *Kh, *Vh, *Vt, *Xh;
    cudaGetSymbolAddress((void**)&Mb, g_mbias);
    cudaGetSymbolAddress((void**)&A16q, g_A16q);
    cudaGetSymbolAddress((void**)&A16k, g_A16k);
    cudaGetSymbolAddress((void**)&A16v, g_A16v);
    cudaGetSymbolAddress((void**)&W16, g_W16);
    cudaGetSymbolAddress((void**)&W16o, g_W16o);
    cudaGetSymbolAddress((void**)&Qh, g_Qh);
    cudaGetSymbolAddress((void**)&Kh, g_Kh);
    cudaGetSymbolAddress((void**)&Vh, g_Vh);
    cudaGetSymbolAddress((void**)&Vt, g_Vt);
    cudaGetSymbolAddress((void**)&Xh, g_Xh);

    build_mask<<<1, 1024>>>(kpm, am, Mb);

    cudaFuncSetAttribute(gemm_qkv, cudaFuncAttributeMaxDynamicSharedMemorySize, QSMEM);
    cudaFuncSetAttribute(gemm_out, cudaFuncAttributeMaxDynamicSharedMemorySize, QSMEM);
    cudaFuncSetAttribute(flash_mma, cudaFuncAttributeMaxDynamicSharedMemorySize, FSMEM);

    const int nA4 = NTOK * D_ / 4;   // 1,048,576
    const int nW4 = D_ * D_ / 4;     // 262,144

    // one fused conversion launch: q, k, v, Wq, Wk, Wv, Wo
    ConvArgs ca;
    ca.in[0] = (const float4*)query; ca.out[0] = (__half2*)A16q; ca.n4[0] = nA4;
    ca.in[1] = (const float4*)key;   ca.out[1] = (__half2*)A16k; ca.n4[1] = nA4;
    ca.in[2] = (const float4*)value; ca.out[2] = (__half2*)A16v; ca.n4[2] = nA4;
    ca.in[3] = (const float4*)Wq; ca.out[3] = (__half2*)(W16 + 0 * (size_t)D_ * D_); ca.n4[3] = nW4;
    ca.in[4] = (const float4*)Wk; ca.out[4] = (__half2*)(W16 + 1 * (size_t)D_ * D_); ca.n4[4] = nW4;
    ca.in[5] = (const float4*)Wv; ca.out[5] = (__half2*)(W16 + 2 * (size_t)D_ * D_); ca.n4[5] = nW4;
    ca.in[6] = (const float4*)Wo; ca.out[6] = (__half2*)W16o; ca.n4[6] = nW4;
    const int ntot = 3 * nA4 + 4 * nW4;
    conv_all<<<(ntot + 255) / 256, 256>>>(ca);

    // fused QKV projections -> Qh (scaled), Kh, Vh
    gemm_qkv<<<dim3(24, NTOK / 128), 256, QSMEM>>>(A16q, A16k, A16v, W16,
                                                   bq, bk, bv, Qh, Kh, Vh);

    // V transpose per head, then flash -> Xh (f16)
    conv_vt16<<<dim3(S_ / 32, HD_ / 32, B_ * H_), dim3(32, 8)>>>(Vh, Vt);
    flash_mma<<<dim3(S_ / 128, H_, B_), 256, FSMEM>>>(Qh, Kh, Vt, Mb, Xh);

    // output projection: fp16 single product
    gemm_out<<<dim3(D_ / 128, NTOK / 128), 256, QSMEM>>>(Xh, W16o, bo, out);
}

// round 16
// speedup vs baseline: 11.6323x; 1.7465x over previous
#include <cuda_runtime.h>
#include <cuda_fp16.h>
#include <cstdint>

// Problem dims (fixed by reference)
#define B_   2
#define S_   2048
#define D_   1024
#define H_   16
#define HD_  64
#define NTOK (B_ * S_)   // 4096

#define QSCALE 0.18033688f   // 0.125 * log2(e): scores in log2 domain

// ---------------- scratch (no cudaMalloc allowed) ----------------
__device__ float g_mbias[NTOK];            // compacted additive bias
__device__ int   g_cnt[B_];                // unmasked key count per batch
__device__ int   g_idx[NTOK];              // compacted key index -> original s
__device__ __half g_A16q[(size_t)NTOK * D_];
__device__ __half g_A16k[(size_t)NTOK * D_];   // gathered (compacted) key input
__device__ __half g_A16v[(size_t)NTOK * D_];   // gathered (compacted) value input
__device__ __half g_W16[(size_t)3 * D_ * D_];  // Wq, Wk, Wv
__device__ __half g_W16o[(size_t)D_ * D_];     // Wo
__device__ __half g_Qh[(size_t)NTOK * D_];
__device__ __half g_Kh[(size_t)NTOK * D_];     // compacted
__device__ __half g_Vh[(size_t)NTOK * D_];     // compacted
__device__ __half g_Vt[(size_t)NTOK * D_];     // [B,H,HD,S] compacted cols
__device__ __half g_Xh[(size_t)NTOK * D_];

// ================= helpers =================
__device__ __forceinline__ uint32_t smem_u32(const void* p) {
    uint32_t a;
    asm("{ .reg .u64 t; cvta.to.shared.u64 t, %1; cvt.u32.u64 %0, t; }"
        : "=r"(a) : "l"(p));
    return a;
}
#define SW128(o) ((o) ^ (((o) >> 3) & 0x70))

#define CP_ASYNC16(dst, src) \
    asm volatile("cp.async.cg.shared.global [%0], [%1], 16;" :: "r"(dst), "l"(src))
#define CP_COMMIT() asm volatile("cp.async.commit_group;" ::: "memory")
#define CP_WAIT(n)  asm volatile("cp.async.wait_group %0;" :: "n"(n) : "memory")

__device__ __forceinline__ void ldsm4(uint32_t* r, uint32_t addr) {
    asm volatile("ldmatrix.sync.aligned.m8n8.x4.shared.b16 {%0,%1,%2,%3}, [%4];"
                 : "=r"(r[0]), "=r"(r[1]), "=r"(r[2]), "=r"(r[3]) : "r"(addr));
}
__device__ __forceinline__ void mma_f16(float* c, const uint32_t* a, const uint32_t* b) {
    asm volatile("mma.sync.aligned.m16n8k16.row.col.f32.f16.f16.f32 "
                 "{%0,%1,%2,%3}, {%4,%5,%6,%7}, {%8,%9}, {%0,%1,%2,%3};"
                 : "+f"(c[0]), "+f"(c[1]), "+f"(c[2]), "+f"(c[3])
                 : "r"(a[0]), "r"(a[1]), "r"(a[2]), "r"(a[3]),
                   "r"(b[0]), "r"(b[1]));
}
__device__ __forceinline__ uint32_t pack_f16x2(float lo, float hi) {
    uint32_t d;
    asm("cvt.rn.f16x2.f32 %0, %1, %2;" : "=r"(d) : "f"(hi), "f"(lo));
    return d;
}
__device__ __forceinline__ uint32_t ex2_f16x2(uint32_t x) {
    uint32_t d;
    asm("ex2.approx.f16x2 %0, %1;" : "=r"(d) : "r"(x));
    return d;
}
__device__ __forceinline__ float ex2f(float x) {
    float y;
    asm("ex2.approx.f32 %0, %1;" : "=f"(y) : "f"(x));
    return y;
}

// =================================================================
// Mask build + key compaction. One block per batch, 1024 threads.
// Produces: cnt[b], idx[b*S+j] (stable order), mbias_c[b*S+j].
// dtype auto-detect (packed uint8 vs int32) as before.
// =================================================================
__global__ void build_mask_compact(const void* __restrict__ kpm_raw,
                                   const void* __restrict__ am_raw,
                                   int* __restrict__ cnt,
                                   int* __restrict__ idxbuf,
                                   float* __restrict__ mbias_c) {
    const int b   = blockIdx.x;
    const int tid = threadIdx.x;
    __shared__ int s_u8;
    __shared__ int warp_sums[32];
    __shared__ int warp_offs[32];
    __shared__ int s_total;

    if (tid == 0) s_u8 = 0;
    __syncthreads();
    const int* probe = (const int*)kpm_raw;
    for (int i = tid; i < 1024; i += 1024)
        if ((unsigned)probe[i] > 1u) s_u8 = 1;
    __syncthreads();
    const int is_u8 = s_u8;

    auto masked = [&](int e) -> int {
        const int g = b * S_ + e;
        int k, a;
        if (is_u8) {
            k = ((const uint8_t*)kpm_raw)[g];
            a = ((const uint8_t*)am_raw)[g];
        } else {
            k = ((const int*)kpm_raw)[g];
            a = ((const int*)am_raw)[g];
        }
        return (k | a) ? 1 : 0;
    };

    // each thread owns elements 2*tid, 2*tid+1
    const int e0 = 2 * tid, e1 = 2 * tid + 1;
    const int f0 = 1 - masked(e0);
    const int f1 = 1 - masked(e1);
    const int mysum = f0 + f1;

    const int lane = tid & 31, w = tid >> 5;
    int incl = mysum;
#pragma unroll
    for (int o = 1; o < 32; o <<= 1) {
        int v = __shfl_up_sync(0xffffffffu, incl, o);
        if (lane >= o) incl += v;
    }
    if (lane == 31) warp_sums[w] = incl;
    __syncthreads();
    if (tid == 0) {
        int acc = 0;
        for (int i = 0; i < 32; i++) { warp_offs[i] = acc; acc += warp_sums[i]; }
        s_total = acc;
        cnt[b] = acc;
    }
    __syncthreads();

    const int excl = warp_offs[w] + incl - mysum;
    if (f0) idxbuf[b * S_ + excl] = e0;
    if (f1) idxbuf[b * S_ + excl + f0] = e1;

    const int total = s_total;
    for (int j = tid; j < S_; j += 1024)
        mbias_c[b * S_ + j] = (j < total) ? 0.0f : -1e30f;
}

// =================================================================
// Gather + convert key/value input rows (compacted), zero pad tail.
// grid (S_, B_), 128 threads.
// =================================================================
__global__ void gather_kv(const float* __restrict__ key,
                          const float* __restrict__ value,
                          const int* __restrict__ idxbuf,
                          const int* __restrict__ cnt,
                          __half* __restrict__ Kc, __half* __restrict__ Vc) {
    const int b = blockIdx.y;
    const int j = blockIdx.x;
    const int c = cnt[b];
    const int cpad = (c + 127) & ~127;
    const int t = threadIdx.x;

    if (j < c) {
        const int s = idxbuf[b * S_ + j];
        const float4* kr = (const float4*)(key   + (size_t)(b * S_ + s) * D_);
        const float4* vr = (const float4*)(value + (size_t)(b * S_ + s) * D_);
        __half2* ko = (__half2*)(Kc + (size_t)(b * S_ + j) * D_);
        __half2* vo = (__half2*)(Vc + (size_t)(b * S_ + j) * D_);
#pragma unroll
        for (int i = t; i < 256; i += 128) {
            float4 x = kr[i];
            ko[2 * i + 0] = __floats2half2_rn(x.x, x.y);
            ko[2 * i + 1] = __floats2half2_rn(x.z, x.w);
            float4 y = vr[i];
            vo[2 * i + 0] = __floats2half2_rn(y.x, y.y);
            vo[2 * i + 1] = __floats2half2_rn(y.z, y.w);
        }
    } else if (j < cpad) {
        __half2 z = __floats2half2_rn(0.0f, 0.0f);
        __half2* ko = (__half2*)(Kc + (size_t)(b * S_ + j) * D_);
        __half2* vo = (__half2*)(Vc + (size_t)(b * S_ + j) * D_);
#pragma unroll
        for (int i = t; i < 512; i += 128) { ko[i] = z; vo[i] = z; }
    }
}

// =================================================================
// Fused fp32 -> fp16 conversion: query + 4 weight matrices
// =================================================================
struct ConvArgs {
    const float4* in[5];
    __half2*      out[5];
    int           n4[5];
};

__global__ void conv_all(ConvArgs args) {
    int i = blockIdx.x * blockDim.x + threadIdx.x;
#pragma unroll
    for (int s = 0; s < 5; s++) {
        if (i < args.n4[s]) {
            float4 v = args.in[s][i];
            args.out[s][2 * i + 0] = __floats2half2_rn(v.x, v.y);
            args.out[s][2 * i + 1] = __floats2half2_rn(v.z, v.w);
            return;
        }
        i -= args.n4[s];
    }
}

// Vh f16 [b*S+j][h*64+d] -> f16 [ (bh*64+d)*S + j ]  (compacted cols)
__global__ void conv_vt16(const __half* __restrict__ V, __half* __restrict__ Vt,
                          const int* __restrict__ cnt) {
    __shared__ __half tile[32][34];
    const int s0 = blockIdx.x * 32;
    const int bh = blockIdx.z;
    const int b = bh >> 4, h = bh & 15;
    const int cpad = (cnt[b] + 127) & ~127;
    if (s0 >= cpad) return;
    const int d0 = blockIdx.y * 32;
    const int tx = threadIdx.x, ty = threadIdx.y;
#pragma unroll
    for (int i = 0; i < 4; i++) {
        const int s = s0 + ty + i * 8;
        tile[ty + i * 8][tx] = V[(size_t)(b * S_ + s) * D_ + h * HD_ + d0 + tx];
    }
    __syncthreads();
#pragma unroll
    for (int i = 0; i < 4; i++) {
        const int d = d0 + ty + i * 8;
        Vt[(size_t)(bh * HD_ + d) * S_ + s0 + tx] = tile[tx][ty + i * 8];
    }
}

// =================================================================
// Fused QKV projection GEMM, fp16 single product.
// grid (24, 32): blockIdx.x -> [section 0..2][n-tile 0..7].
// K/V sections operate on compacted rows; early-exit beyond pad.
// =================================================================
#define QTILE_B 16384
#define QSTG_B  (2 * QTILE_B)
#define QSMEM   (2 * QSTG_B)     // 65536
#define KSTEPS  16

__global__ __launch_bounds__(256, 2)
void gemm_qkv(const __half* __restrict__ Aq, const __half* __restrict__ Ak,
              const __half* __restrict__ Av, const __half* __restrict__ W16,
              const float* __restrict__ bq, const float* __restrict__ bk,
              const float* __restrict__ bv, const int* __restrict__ cnt,
              __half* __restrict__ Qh, __half* __restrict__ Kh,
              __half* __restrict__ Vh) {
    const int sec = blockIdx.x >> 3;
    if (sec > 0) {
        const int bb = blockIdx.y >> 4;
        const int lt = blockIdx.y & 15;
        const int cpad = (cnt[bb] + 127) & ~127;
        if (lt * 128 >= cpad) return;
    }

    extern __shared__ char smem[];
    const uint32_t sb = smem_u32(smem);
    const int tid  = threadIdx.x;
    const int wid  = tid >> 5;
    const int lane = tid & 31;
    const int wm = wid & 1;
    const int wn = wid >> 1;

    const int bxn = blockIdx.x & 7;
    const __half* A = (sec == 0) ? Aq : (sec == 1) ? Ak : Av;
    const __half* W = W16 + (size_t)sec * D_ * D_ + (size_t)bxn * 128 * D_;
    const float* bias = ((sec == 0) ? bq : (sec == 1) ? bk : bv) + bxn * 128;
    __half* C = (sec == 0) ? Qh : (sec == 1) ? Kh : Vh;
    const float csc = (sec == 0) ? QSCALE : 1.0f;

    A += (size_t)blockIdx.y * 128 * D_;

    const int crow = tid >> 3;
    const int c16  = tid & 7;

    auto load_stage = [&](int ks, int stage) {
        const uint32_t stb = sb + stage * QSTG_B;
        const __half* gA = A + (size_t)ks * 64 + c16 * 8;
        const __half* gW = W + (size_t)ks * 64 + c16 * 8;
#pragma unroll
        for (int p = 0; p < 4; p++) {
            const int row = crow + p * 32;
            const uint32_t so = SW128((uint32_t)(row * 128 + c16 * 16));
            CP_ASYNC16(stb + so, gA + (size_t)row * D_);
            CP_ASYNC16(stb + QTILE_B + so, gW + (size_t)row * D_);
        }
    };

    float acc[4][4][4] = {};
    load_stage(0, 0);
    CP_COMMIT();

    for (int ks = 0; ks < KSTEPS; ks++) {
        const int stage = ks & 1;
        if (ks + 1 < KSTEPS) {
            load_stage(ks + 1, stage ^ 1);
            CP_COMMIT();
            CP_WAIT(1);
        } else {
            CP_WAIT(0);
        }
        __syncthreads();

        const uint32_t sA = sb + stage * QSTG_B;
        const uint32_t sW = sA + QTILE_B;

#pragma unroll
        for (int kk = 0; kk < 4; kk++) {
            const uint32_t bcol = kk * 32 + ((lane >> 4) << 4);
            uint32_t bh[4][2];
#pragma unroll
            for (int nb = 0; nb < 2; nb++) {
                const int row = wn * 32 + nb * 16 + (lane & 15);
                uint32_t r4[4];
                ldsm4(r4, sW + SW128((uint32_t)(row * 128) + bcol));
                bh[2 * nb][0] = r4[0]; bh[2 * nb][1] = r4[2];
                bh[2 * nb + 1][0] = r4[1]; bh[2 * nb + 1][1] = r4[3];
            }
#pragma unroll
            for (int mf = 0; mf < 4; mf++) {
                const int row = wm * 64 + mf * 16 + (lane & 15);
                uint32_t ah[4];
                ldsm4(ah, sA + SW128((uint32_t)(row * 128) + bcol));
#pragma unroll
                for (int nf = 0; nf < 4; nf++)
                    mma_f16(acc[mf][nf], ah, bh[nf]);
            }
        }
        __syncthreads();
    }

    const int r  = lane >> 2;
    const int c2 = (lane & 3) * 2;
#pragma unroll
    for (int nf = 0; nf < 4; nf++) {
        const int lcol = bxn * 128 + wn * 32 + nf * 8 + c2;
        const float b0 = __ldg(bias + wn * 32 + nf * 8 + c2);
        const float b1 = __ldg(bias + wn * 32 + nf * 8 + c2 + 1);
#pragma unroll
        for (int mf = 0; mf < 4; mf++) {
            const int grow = blockIdx.y * 128 + wm * 64 + mf * 16 + r;
            __half2 v0 = __floats2half2_rn((acc[mf][nf][0] + b0) * csc,
                                           (acc[mf][nf][1] + b1) * csc);
            __half2 v1 = __floats2half2_rn((acc[mf][nf][2] + b0) * csc,
                                           (acc[mf][nf][3] + b1) * csc);
            *(__half2*)(C + (size_t)grow * D_ + lcol) = v0;
            *(__half2*)(C + (size_t)(grow + 8) * D_ + lcol) = v1;
        }
    }
}

// =================================================================
// Output projection GEMM, fp16 single product, fp32 output.
// =================================================================
__global__ __launch_bounds__(256, 2)
void gemm_out(const __half* __restrict__ Xh, const __half* __restrict__ Wo16,
              const float* __restrict__ bias, float* __restrict__ C) {
    extern __shared__ char smem[];
    const uint32_t sb = smem_u32(smem);
    const int tid  = threadIdx.x;
    const int wid  = tid >> 5;
    const int lane = tid & 31;
    const int wm = wid & 1;
    const int wn = wid >> 1;

    const __half* A = Xh + (size_t)blockIdx.y * 128 * D_;
    const __half* W = Wo16 + (size_t)blockIdx.x * 128 * D_;

    const int crow = tid >> 3;
    const int c16  = tid & 7;

    auto load_stage = [&](int ks, int stage) {
        const uint32_t stb = sb + stage * QSTG_B;
        const __half* gA = A + (size_t)ks * 64 + c16 * 8;
        const __half* gW = W + (size_t)ks * 64 + c16 * 8;
#pragma unroll
        for (int p = 0; p < 4; p++) {
            const int row = crow + p * 32;
            const uint32_t so = SW128((uint32_t)(row * 128 + c16 * 16));
            CP_ASYNC16(stb + so, gA + (size_t)row * D_);
            CP_ASYNC16(stb + QTILE_B + so, gW + (size_t)row * D_);
        }
    };

    float acc[4][4][4] = {};
    load_stage(0, 0);
    CP_COMMIT();

    for (int ks = 0; ks < KSTEPS; ks++) {
        const int stage = ks & 1;
        if (ks + 1 < KSTEPS) {
            load_stage(ks + 1, stage ^ 1);
            CP_COMMIT();
            CP_WAIT(1);
        } else {
            CP_WAIT(0);
        }
        __syncthreads();

        const uint32_t sA = sb + stage * QSTG_B;
        const uint32_t sW = sA + QTILE_B;

#pragma unroll
        for (int kk = 0; kk < 4; kk++) {
            const uint32_t bcol = kk * 32 + ((lane >> 4) << 4);
            uint32_t bh[4][2];
#pragma unroll
            for (int nb = 0; nb < 2; nb++) {
                const int row = wn * 32 + nb * 16 + (lane & 15);
                uint32_t r4[4];
                ldsm4(r4, sW + SW128((uint32_t)(row * 128) + bcol));
                bh[2 * nb][0] = r4[0]; bh[2 * nb][1] = r4[2];
                bh[2 * nb + 1][0] = r4[1]; bh[2 * nb + 1][1] = r4[3];
            }
#pragma unroll
            for (int mf = 0; mf < 4; mf++) {
                const int row = wm * 64 + mf * 16 + (lane & 15);
                uint32_t ah[4];
                ldsm4(ah, sA + SW128((uint32_t)(row * 128) + bcol));
#pragma unroll
                for (int nf = 0; nf < 4; nf++)
                    mma_f16(acc[mf][nf], ah, bh[nf]);
            }
        }
        __syncthreads();
    }

    const int r  = lane >> 2;
    const int c2 = (lane & 3) * 2;
#pragma unroll
    for (int nf = 0; nf < 4; nf++) {
        const int gcol = blockIdx.x * 128 + wn * 32 + nf * 8 + c2;
        const float b0 = __ldg(bias + gcol);
        const float b1 = __ldg(bias + gcol + 1);
#pragma unroll
        for (int mf = 0; mf < 4; mf++) {
            const int grow = blockIdx.y * 128 + wm * 64 + mf * 16 + r;
            float2 v0 = {acc[mf][nf][0] + b0, acc[mf][nf][1] + b1};
            float2 v1 = {acc[mf][nf][2] + b0, acc[mf][nf][3] + b1};
            *(float2*)(C + (size_t)grow * D_ + gcol) = v0;
            *(float2*)(C + (size_t)(grow + 8) * D_ + gcol) = v1;
        }
    }
}

// =================================================================
// Flash attention over COMPACTED keys. nkt = ceil(cnt/64) tiles.
// fp16 mma, log2-domain softmax, ones-MMA row sums. Writes X as f16.
// =================================================================
#define FSQ   0
#define FSK   16384
#define FSV   (16384 + 16384)
#define FSMB  (FSV + 16384)
#define FSMEM (FSMB + 512)

__global__ __launch_bounds__(256, 1)
void flash_mma(const __half* __restrict__ Qh, const __half* __restrict__ Kh,
               const __half* __restrict__ Vt, const float* __restrict__ mbias,
               const int* __restrict__ cnt, __half* __restrict__ O) {
    extern __shared__ char smem[];
    const uint32_t sb = smem_u32(smem);
    const int tid  = threadIdx.x;
    const int wid  = tid >> 5;
    const int lane = tid & 31;
    const int q0 = blockIdx.x * 128;
    const int h  = blockIdx.y;
    const int b  = blockIdx.z;

    const int nkt = (cnt[b] + 63) >> 6;

    const int crow = tid >> 3;
    const int c16  = tid & 7;

    const __half* Qg = Qh + (size_t)(b * S_ + q0) * D_ + h * HD_;
    const __half* Kg = Kh + (size_t)b * S_ * D_ + h * HD_;
    const __half* Vg = Vt + (size_t)(b * H_ + h) * HD_ * S_;
    const float*  Mg = mbias + b * S_;

#pragma unroll
    for (int p = 0; p < 4; p++) {
        const int row = crow + p * 32;
        CP_ASYNC16(sb + FSQ + SW128((uint32_t)(row * 128 + c16 * 16)),
                   Qg + (size_t)row * D_ + c16 * 8);
    }
    auto load_stage = [&](int kt, int st) {
#pragma unroll
        for (int p = 0; p < 2; p++) {
            const int row = crow + p * 32;
            const uint32_t so = SW128((uint32_t)(row * 128 + c16 * 16));
            CP_ASYNC16(sb + FSK + st * 8192 + so,
                       Kg + (size_t)(kt * 64 + row) * D_ + c16 * 8);
            CP_ASYNC16(sb + FSV + st * 8192 + so,
                       Vg + (size_t)row * S_ + kt * 64 + c16 * 8);
        }
        if (tid < 16)
            CP_ASYNC16(sb + FSMB + st * 256 + tid * 16, Mg + kt * 64 + tid * 4);
    };
    load_stage(0, 0);
    CP_COMMIT();

    uint32_t qf[4][4];
    float o[8][4] = {};
    float lfrag[4] = {};
    float m0 = -1e30f, m1 = -1e30f;
    const uint32_t ones2[2] = {0x3C003C00u, 0x3C003C00u};

    const int lrow = lane & 15;
    const uint32_t lcol = (uint32_t)((lane >> 4) << 4);

    for (int kt = 0; kt < nkt; kt++) {
        const int st = kt & 1;
        if (kt + 1 < nkt) {
            load_stage(kt + 1, st ^ 1);
            CP_COMMIT();
            CP_WAIT(1);
        } else {
            CP_WAIT(0);
        }
        __syncthreads();

        if (kt == 0) {
#pragma unroll
            for (int ks = 0; ks < 4; ks++)
                ldsm4(qf[ks], sb + FSQ +
                      SW128((uint32_t)((wid * 16 + lrow) * 128 + ks * 32) + lcol));
        }

        const uint32_t sbK = sb + FSK + st * 8192;
        const uint32_t sbV = sb + FSV + st * 8192;
        const float* mbp = (const float*)(smem + FSMB + st * 256);

        // ---- S = Q K^T (log2 domain) ----
        float s[8][4] = {};
#pragma unroll
        for (int ks = 0; ks < 4; ks++) {
#pragma unroll
            for (int nb = 0; nb < 4; nb++) {
                uint32_t r4[4];
                ldsm4(r4, sbK + SW128((uint32_t)((nb * 16 + lrow) * 128 + ks * 32) + lcol));
                uint32_t b0[2] = {r4[0], r4[2]};
                uint32_t b1[2] = {r4[1], r4[3]};
                mma_f16(s[2 * nb], qf[ks], b0);
                mma_f16(s[2 * nb + 1], qf[ks], b1);
            }
        }

        // ---- mask + running max ----
        const int cbase = (lane & 3) * 2;
        float tm0 = -3e38f, tm1 = -3e38f;
#pragma unroll
        for (int nf = 0; nf < 8; nf++) {
            float2 mv = *(const float2*)(mbp + nf * 8 + cbase);
            s[nf][0] += mv.x; s[nf][1] += mv.y;
            s[nf][2] += mv.x; s[nf][3] += mv.y;
            tm0 = fmaxf(tm0, fmaxf(s[nf][0], s[nf][1]));
            tm1 = fmaxf(tm1, fmaxf(s[nf][2], s[nf][3]));
        }
        tm0 = fmaxf(tm0, __shfl_xor_sync(0xffffffffu, tm0, 1));
        tm0 = fmaxf(tm0, __shfl_xor_sync(0xffffffffu, tm0, 2));
        tm1 = fmaxf(tm1, __shfl_xor_sync(0xffffffffu, tm1, 1));
        tm1 = fmaxf(tm1, __shfl_xor_sync(0xffffffffu, tm1, 2));

        const float mn0 = fmaxf(m0, tm0);
        const float mn1 = fmaxf(m1, tm1);
        const float cr0 = ex2f(m0 - mn0);
        const float cr1 = ex2f(m1 - mn1);
        m0 = mn0; m1 = mn1;

        // ---- P = 2^(S-m) as f16x2 fragments ----
        uint32_t pa[4][4];
#pragma unroll
        for (int nf = 0; nf < 8; nf++) {
            uint32_t x01 = pack_f16x2(s[nf][0] - m0, s[nf][1] - m0);
            uint32_t x23 = pack_f16x2(s[nf][2] - m1, s[nf][3] - m1);
            const int kk = nf >> 1;
            if ((nf & 1) == 0) {
                pa[kk][0] = ex2_f16x2(x01);
                pa[kk][1] = ex2_f16x2(x23);
            } else {
                pa[kk][2] = ex2_f16x2(x01);
                pa[kk][3] = ex2_f16x2(x23);
            }
        }

        // ---- rescale O, l ----
#pragma unroll
        for (int nf = 0; nf < 8; nf++) {
            o[nf][0] *= cr0; o[nf][1] *= cr0;
            o[nf][2] *= cr1; o[nf][3] *= cr1;
        }
        lfrag[0] *= cr0; lfrag[1] *= cr0;
        lfrag[2] *= cr1; lfrag[3] *= cr1;

        // ---- l += P * ones ----
#pragma unroll
        for (int kk = 0; kk < 4; kk++)
            mma_f16(lfrag, pa[kk], ones2);

        // ---- O += P V ----
#pragma unroll
        for (int kk = 0; kk < 4; kk++) {
#pragma unroll
            for (int nb = 0; nb < 4; nb++) {
                uint32_t r4[4];
                ldsm4(r4, sbV + SW128((uint32_t)((nb * 16 + lrow) * 128 + kk * 32) + lcol));
                uint32_t b0[2] = {r4[0], r4[2]};
                uint32_t b1[2] = {r4[1], r4[3]};
                mma_f16(o[2 * nb], pa[kk], b0);
                mma_f16(o[2 * nb + 1], pa[kk], b1);
            }
        }
        __syncthreads();
    }

    // ---- write X as f16 ----
    const float inv0 = 1.0f / lfrag[0];
    const float inv1 = 1.0f / lfrag[2];
    const int r = lane >> 2;
    const int tok0 = b * S_ + q0 + wid * 16 + r;
#pragma unroll
    for (int nf = 0; nf < 8; nf++) {
        const int col = h * HD_ + nf * 8 + (lane & 3) * 2;
        *(__half2*)(O + (size_t)tok0 * D_ + col) =
            __floats2half2_rn(o[nf][0] * inv0, o[nf][1] * inv0);
        *(__half2*)(O + (size_t)(tok0 + 8) * D_ + col) =
            __floats2half2_rn(o[nf][2] * inv1, o[nf][3] * inv1);
    }
}

// =================================================================
// launch
// =================================================================
extern "C" void kernel_launch(void* const* d_in, const int* in_sizes, int n_in,
                              void* d_out, int out_size) {
    const float* query = (const float*)d_in[0];
    const float* key   = (const float*)d_in[1];
    const float* value = (const float*)d_in[2];
    const void*  kpm   = d_in[3];
    const void*  am    = d_in[4];
    // d_in[5] = is_casual (ignored in eval mode)
    const float* Wq = (const float*)d_in[6];
    const float* bq = (const float*)d_in[7];
    const float* Wk = (const float*)d_in[8];
    const float* bk = (const float*)d_in[9];
    const float* Wv = (const float*)d_in[10];
    const float* bv = (const float*)d_in[11];
    const float* Wo = (const float*)d_in[12];
    const float* bo = (const float*)d_in[13];
    float* out = (float*)d_out;

    float* Mb;
    int *Cnt, *Idx;
    __half *A16q, *A16k, *A16v, *W16, *W16o, *Qh, *Kh, *Vh, *Vt, *Xh;
    cudaGetSymbolAddress((void**)&Mb, g_mbias);
    cudaGetSymbolAddress((void**)&Cnt, g_cnt);
    cudaGetSymbolAddress((void**)&Idx, g_idx);
    cudaGetSymbolAddress((void**)&A16q, g_A16q);
    cudaGetSymbolAddress((void**)&A16k, g_A16k);
    cudaGetSymbolAddress((void**)&A16v, g_A16v);
    cudaGetSymbolAddress((void**)&W16, g_W16);
    cudaGetSymbolAddress((void**)&W16o, g_W16o);
    cudaGetSymbolAddress((void**)&Qh, g_Qh);
    cudaGetSymbolAddress((void**)&Kh, g_Kh);
    cudaGetSymbolAddress((void**)&Vh, g_Vh);
    cudaGetSymbolAddress((void**)&Vt, g_Vt);
    cudaGetSymbolAddress((void**)&Xh, g_Xh);

    cudaFuncSetAttribute(gemm_qkv, cudaFuncAttributeMaxDynamicSharedMemorySize, QSMEM);
    cudaFuncSetAttribute(gemm_out, cudaFuncAttributeMaxDynamicSharedMemorySize, QSMEM);
    cudaFuncSetAttribute(flash_mma, cudaFuncAttributeMaxDynamicSharedMemorySize, FSMEM);

    const int nA4 = NTOK * D_ / 4;
    const int nW4 = D_ * D_ / 4;

    // mask compaction (independent of conversions)
    build_mask_compact<<<B_, 1024>>>(kpm, am, Cnt, Idx, Mb);

    // conversions: query + all weights
    ConvArgs ca;
    ca.in[0] = (const float4*)query; ca.out[0] = (__half2*)A16q; ca.n4[0] = nA4;
    ca.in[1] = (const float4*)Wq; ca.out[1] = (__half2*)(W16 + 0 * (size_t)D_ * D_); ca.n4[1] = nW4;
    ca.in[2] = (const float4*)Wk; ca.out[2] = (__half2*)(W16 + 1 * (size_t)D_ * D_); ca.n4[2] = nW4;
    ca.in[3] = (const float4*)Wv; ca.out[3] = (__half2*)(W16 + 2 * (size_t)D_ * D_); ca.n4[3] = nW4;
    ca.in[4] = (const float4*)Wo; ca.out[4] = (__half2*)W16o; ca.n4[4] = nW4;
    const int ntot = nA4 + 4 * nW4;
    conv_all<<<(ntot + 255) / 256, 256>>>(ca);

    // gather + convert compacted key/value inputs
    gather_kv<<<dim3(S_, B_), 128>>>(key, value, Idx, Cnt, A16k, A16v);

    // fused QKV projections (K/V compacted)
    gemm_qkv<<<dim3(24, NTOK / 128), 256, QSMEM>>>(A16q, A16k, A16v, W16,
                                                   bq, bk, bv, Cnt, Qh, Kh, Vh);

    // V transpose (compacted), then flash -> Xh
    conv_vt16<<<dim3(S_ / 32, HD_ / 32, B_ * H_), dim3(32, 8)>>>(Vh, Vt, Cnt);
    flash_mma<<<dim3(S_ / 128, H_, B_), 256, FSMEM>>>(Qh, Kh, Vt, Mb, Cnt, Xh);

    // output projection
    gemm_out<<<dim3(D_ / 128, NTOK / 128), 256, QSMEM>>>(Xh, W16o, bo, out);
}